// round 5
// baseline (speedup 1.0000x reference)
#include <cuda_runtime.h>
#include <cuda_bf16.h>
#include <cstdint>
#include <cstddef>
#include <math.h>

#define NB   32      // batch
#define T1   2000    // layer-1 time steps
#define T2   1000    // layer-2 time steps (after pool s=2)
#define D1   80      // input feature dim
#define HH   256     // hidden per direction
#define G4H  1024    // 4*H gate rows
#define HDC  512     // 2*H (bidirectional concat)
#define OUTC 512     // final output channels
#define NBLK 128     // persistent LSTM blocks

typedef unsigned long long ull;

// ---------------- f32x2 packed-FMA helpers (Blackwell FFMA2) -----------------
__device__ __forceinline__ void fma2(ull& d, ull a, ull b) {
    asm("fma.rn.f32x2 %0, %1, %2, %3;" : "=l"(d) : "l"(a), "l"(b), "l"(d));
}
__device__ __forceinline__ ull dup2(float x) {
    ull r; asm("mov.b64 %0, {%1, %1};" : "=l"(r) : "f"(x)); return r;
}
__device__ __forceinline__ float2 unp2(ull v) {
    float2 r; asm("mov.b64 {%0, %1}, %2;" : "=f"(r.x), "=f"(r.y) : "l"(v)); return r;
}
__device__ __forceinline__ ulonglong2 ldcg2(const ulonglong2* p) {
    ulonglong2 v;
    asm volatile("ld.global.cg.v2.u64 {%0,%1}, [%2];" : "=l"(v.x), "=l"(v.y) : "l"(p));
    return v;
}

// ---------------- device scratch (static: allocation is forbidden) ----------
__device__ float g_xg1f[(size_t)T1 * G4H * NB];   // [t][gate_row][b]
__device__ float g_xg1b[(size_t)T1 * G4H * NB];
__device__ float g_xg2f[(size_t)T2 * G4H * NB];
__device__ float g_xg2b[(size_t)T2 * G4H * NB];
__device__ float g_out1[(size_t)NB * T1 * HDC];   // [b][t][ch]
__device__ float g_pool1[(size_t)NB * T2 * HDC];
__device__ float g_out2[(size_t)NB * T2 * HDC];
__device__ float g_hbuf[2 * 2 * HH * NB];         // [dir][parity][k][b]
__device__ volatile unsigned g_arr[NBLK * 32];    // arrival flags, 128B stride
__device__ volatile unsigned g_rel;               // release generation

// ---------------- small helpers ---------------------------------------------
__global__ void k_zero(float* __restrict__ p, size_t n) {
    size_t i = (size_t)blockIdx.x * blockDim.x + threadIdx.x;
    size_t st = (size_t)gridDim.x * blockDim.x;
    for (; i < n; i += st) p[i] = 0.f;
}

__global__ void k_init_rec() {
    for (int j = threadIdx.x; j < 2 * 2 * HH * NB; j += blockDim.x) g_hbuf[j] = 0.f;
    for (int j = threadIdx.x; j < NBLK * 32; j += blockDim.x) g_arr[j] = 0u;
    if (threadIdx.x == 0) g_rel = 0u;
}

__global__ void k_pool(const float* __restrict__ in, float* __restrict__ out) {
    size_t n = (size_t)NB * T2 * HDC;
    size_t i = (size_t)blockIdx.x * blockDim.x + threadIdx.x;
    size_t st = (size_t)gridDim.x * blockDim.x;
    for (; i < n; i += st) {
        int c  = (int)(i % HDC);
        size_t r = i / HDC;
        int tp = (int)(r % T2);
        int b  = (int)(r / T2);
        const float* p = in + ((size_t)b * T1 + 2 * (size_t)tp) * HDC + c;
        out[i] = fmaxf(p[0], p[HDC]);
    }
}

__global__ void k_lens(const int* __restrict__ xlen, float* __restrict__ out) {
    int i = threadIdx.x;
    if (i < NB) out[i] = (float)(xlen[i] >> 1);
}

// ---------------- projection / linear GEMM ----------------------------------
// C[row][b] at time t: bias[row] + sum_k W[row][k] * X[(b*Tt+t)*K + k]
// Block tile: 256 rows x (one t x 32 b). 128 threads, thread tile 8 rows x 8 b.
// f32x2 packs TWO CONSECUTIVE ROWS per register lane (no smem duplication);
// the b operand is broadcast via register dup (ALU pipe, off the FMA pipe).
// Requires K % 16 == 0, M % 256 == 0 or M % 512... (M in {1024, 512}).
__global__ void __launch_bounds__(128, 2) k_proj(
    const float* __restrict__ X, const float* __restrict__ W,
    const float* __restrict__ bias, float* __restrict__ out,
    int Tt, int K, long long ot, long long orr, long long ob)
{
    __shared__ __align__(16) float a_sh[16][256];   // [k][row]
    __shared__ __align__(16) float b_sh[16][32];    // [k][b]

    const int t    = blockIdx.y;
    const int row0 = blockIdx.x * 256;
    const int tid  = threadIdx.x;
    const int rowg = tid >> 2;   // 0..31 -> rows rowg*8 .. +7
    const int colg = tid & 3;    // 0..3  -> b colg*8 .. +7

    ull acc[4][8];               // [row-pair][b]
#pragma unroll
    for (int i = 0; i < 4; i++)
#pragma unroll
        for (int j = 0; j < 8; j++) acc[i][j] = 0ull;

    for (int k0 = 0; k0 < K; k0 += 16) {
        // stage W chunk: rows row0+tid and row0+tid+128, 16 k, transposed
        {
            const float* wp = W + (size_t)(row0 + tid) * K + k0;
            float4 v0 = ((const float4*)wp)[0];
            float4 v1 = ((const float4*)wp)[1];
            float4 v2 = ((const float4*)wp)[2];
            float4 v3 = ((const float4*)wp)[3];
            a_sh[ 0][tid] = v0.x; a_sh[ 1][tid] = v0.y; a_sh[ 2][tid] = v0.z; a_sh[ 3][tid] = v0.w;
            a_sh[ 4][tid] = v1.x; a_sh[ 5][tid] = v1.y; a_sh[ 6][tid] = v1.z; a_sh[ 7][tid] = v1.w;
            a_sh[ 8][tid] = v2.x; a_sh[ 9][tid] = v2.y; a_sh[10][tid] = v2.z; a_sh[11][tid] = v2.w;
            a_sh[12][tid] = v3.x; a_sh[13][tid] = v3.y; a_sh[14][tid] = v3.z; a_sh[15][tid] = v3.w;
            wp += (size_t)128 * K;
            v0 = ((const float4*)wp)[0];
            v1 = ((const float4*)wp)[1];
            v2 = ((const float4*)wp)[2];
            v3 = ((const float4*)wp)[3];
            const int r2 = tid + 128;
            a_sh[ 0][r2] = v0.x; a_sh[ 1][r2] = v0.y; a_sh[ 2][r2] = v0.z; a_sh[ 3][r2] = v0.w;
            a_sh[ 4][r2] = v1.x; a_sh[ 5][r2] = v1.y; a_sh[ 6][r2] = v1.z; a_sh[ 7][r2] = v1.w;
            a_sh[ 8][r2] = v2.x; a_sh[ 9][r2] = v2.y; a_sh[10][r2] = v2.z; a_sh[11][r2] = v2.w;
            a_sh[12][r2] = v3.x; a_sh[13][r2] = v3.y; a_sh[14][r2] = v3.z; a_sh[15][r2] = v3.w;
        }
        // stage X chunk: 32 b x 16 k, transposed
        {
            const int bb = tid >> 2, ko = (tid & 3) * 4;
            const float* xp = X + ((size_t)bb * Tt + t) * K + k0 + ko;
            float4 u = *(const float4*)xp;
            b_sh[ko + 0][bb] = u.x; b_sh[ko + 1][bb] = u.y;
            b_sh[ko + 2][bb] = u.z; b_sh[ko + 3][bb] = u.w;
        }
        __syncthreads();
#pragma unroll
        for (int kk = 0; kk < 16; kk++) {
            ulonglong2 a01 = *(const ulonglong2*)&a_sh[kk][rowg * 8];       // rows 0-3 as 2 pairs
            ulonglong2 a23 = *(const ulonglong2*)&a_sh[kk][rowg * 8 + 4];   // rows 4-7
            float4 u0 = *(const float4*)&b_sh[kk][colg * 8];
            float4 u1 = *(const float4*)&b_sh[kk][colg * 8 + 4];
            ull b0 = dup2(u0.x), b1 = dup2(u0.y), b2 = dup2(u0.z), b3 = dup2(u0.w);
            ull b4 = dup2(u1.x), b5 = dup2(u1.y), b6 = dup2(u1.z), b7 = dup2(u1.w);
            fma2(acc[0][0], a01.x, b0); fma2(acc[0][1], a01.x, b1);
            fma2(acc[0][2], a01.x, b2); fma2(acc[0][3], a01.x, b3);
            fma2(acc[0][4], a01.x, b4); fma2(acc[0][5], a01.x, b5);
            fma2(acc[0][6], a01.x, b6); fma2(acc[0][7], a01.x, b7);
            fma2(acc[1][0], a01.y, b0); fma2(acc[1][1], a01.y, b1);
            fma2(acc[1][2], a01.y, b2); fma2(acc[1][3], a01.y, b3);
            fma2(acc[1][4], a01.y, b4); fma2(acc[1][5], a01.y, b5);
            fma2(acc[1][6], a01.y, b6); fma2(acc[1][7], a01.y, b7);
            fma2(acc[2][0], a23.x, b0); fma2(acc[2][1], a23.x, b1);
            fma2(acc[2][2], a23.x, b2); fma2(acc[2][3], a23.x, b3);
            fma2(acc[2][4], a23.x, b4); fma2(acc[2][5], a23.x, b5);
            fma2(acc[2][6], a23.x, b6); fma2(acc[2][7], a23.x, b7);
            fma2(acc[3][0], a23.y, b0); fma2(acc[3][1], a23.y, b1);
            fma2(acc[3][2], a23.y, b2); fma2(acc[3][3], a23.y, b3);
            fma2(acc[3][4], a23.y, b4); fma2(acc[3][5], a23.y, b5);
            fma2(acc[3][6], a23.y, b6); fma2(acc[3][7], a23.y, b7);
        }
        __syncthreads();
    }

    // epilogue
    const int rbase = row0 + rowg * 8;
    float4 bv0 = *(const float4*)&bias[rbase];
    float4 bv1 = *(const float4*)&bias[rbase + 4];
    const float bv[8] = {bv0.x, bv0.y, bv0.z, bv0.w, bv1.x, bv1.y, bv1.z, bv1.w};

    if (ob == 1) {
        // xg layout: out[t*ot + row*orr + b], orr = NB -> store along b
        float* op = out + (size_t)t * ot + (size_t)rbase * orr + colg * 8;
#pragma unroll
        for (int rp = 0; rp < 4; rp++) {
            float va[8], vb[8];
#pragma unroll
            for (int c = 0; c < 8; c++) {
                float2 u = unp2(acc[rp][c]);
                va[c] = u.x + bv[2 * rp];
                vb[c] = u.y + bv[2 * rp + 1];
            }
            float* r0 = op + (size_t)(2 * rp) * orr;
            float* r1 = op + (size_t)(2 * rp + 1) * orr;
            *(float4*)r0       = make_float4(va[0], va[1], va[2], va[3]);
            *(float4*)(r0 + 4) = make_float4(va[4], va[5], va[6], va[7]);
            *(float4*)r1       = make_float4(vb[0], vb[1], vb[2], vb[3]);
            *(float4*)(r1 + 4) = make_float4(vb[4], vb[5], vb[6], vb[7]);
        }
    } else {
        // linear layout: out[t*ot + row + b*ob], orr = 1 -> store along row
        float* op = out + (size_t)t * ot + rbase;
#pragma unroll
        for (int c = 0; c < 8; c++) {
            size_t boff = (size_t)(colg * 8 + c) * ob;
            float2 p0 = unp2(acc[0][c]);
            float2 p1 = unp2(acc[1][c]);
            float2 p2 = unp2(acc[2][c]);
            float2 p3 = unp2(acc[3][c]);
            *(float4*)(op + boff)     = make_float4(p0.x + bv[0], p0.y + bv[1], p1.x + bv[2], p1.y + bv[3]);
            *(float4*)(op + boff + 4) = make_float4(p2.x + bv[4], p2.y + bv[5], p3.x + bv[6], p3.y + bv[7]);
        }
    }
}

// ---------------- persistent recurrent LSTM (f32x2) --------------------------
__device__ __forceinline__ float fsig(float x) {
    return 1.f / (1.f + __expf(-x));
}
__device__ __forceinline__ float ftanh(float x) {
    float e = __expf(2.f * x);
    return 1.f - 2.f / (e + 1.f);
}

__global__ void __launch_bounds__(128, 1) k_lstm(
    const float* __restrict__ xgF, const float* __restrict__ xgB,
    const float* __restrict__ WhhF, const float* __restrict__ WhhB,
    const int* __restrict__ xlen, int lenShift,
    float* __restrict__ out, int Tt)
{
    __shared__ __align__(16) ull   w2[HH * 16];      // [k][rr], rr = gate*4+j, duplicated
    __shared__ __align__(16) float part[4 * 16 * NB];

    const int dir = (int)(blockIdx.x >> 6);
    const int gb  = (int)(blockIdx.x & 63);
    const float* xg  = dir ? xgB : xgF;
    const float* Whh = dir ? WhhB : WhhF;
    float* hb = g_hbuf + dir * (2 * HH * NB);

    const int tid  = threadIdx.x;
    const int warp = tid >> 5, lane = tid & 31;
    const int bg = lane >> 2;     // batch group 0..7
    const int rg = lane & 3;      // gate group 0..3
    const int kbase = warp * 64;  // K section per warp

    // stage Whh slice transposed + duplicated
    {
        const int rr = tid & 15, kp = tid >> 4;    // kp 0..7
        const int grow = (rr >> 2) * HH + gb * 4 + (rr & 3);
        const float* wp = Whh + (size_t)grow * HH + kp * 32;
#pragma unroll
        for (int j = 0; j < 32; j++) w2[(size_t)(kp * 32 + j) * 16 + rr] = dup2(wp[j]);
    }

    const int b_pt = lane;
    const int hj   = warp;
    const int hk   = gb * 4 + hj;
    const int len_b = xlen[b_pt] >> lenShift;
    float c_st = 0.f, h_st = 0.f;

    __syncthreads();

    // gate-input prefetch for step 0
    float xg0, xg1, xg2, xg3;
    {
        int tx = dir ? (len_b - 1) : 0;
        if (tx < 0) tx = 0;
        const float* xp = xg + (size_t)tx * (G4H * NB) + (size_t)hk * NB + b_pt;
        xg0 = __ldg(xp);
        xg1 = __ldg(xp + 256 * NB);
        xg2 = __ldg(xp + 512 * NB);
        xg3 = __ldg(xp + 768 * NB);
    }

    for (int s = 0; s < Tt; s++) {
        const float* hrd = hb + (s & 1) * (HH * NB);
        float* hwr = hb + ((s & 1) ^ 1) * (HH * NB);

        // GEMM slice
        ull acc2[4][2] = {};
        const ulonglong2* hp  = (const ulonglong2*)hrd + (size_t)kbase * 8 + bg;
        const ulonglong2* wp2 = (const ulonglong2*)w2 + (size_t)kbase * 8 + rg * 2;
#pragma unroll 8
        for (int k = 0; k < 64; k++) {
            ulonglong2 hv   = ldcg2(hp + (size_t)k * 8);
            ulonglong2 wv01 = wp2[(size_t)k * 8];
            ulonglong2 wv23 = wp2[(size_t)k * 8 + 1];
            fma2(acc2[0][0], wv01.x, hv.x); fma2(acc2[0][1], wv01.x, hv.y);
            fma2(acc2[1][0], wv01.y, hv.x); fma2(acc2[1][1], wv01.y, hv.y);
            fma2(acc2[2][0], wv23.x, hv.x); fma2(acc2[2][1], wv23.x, hv.y);
            fma2(acc2[3][0], wv23.y, hv.x); fma2(acc2[3][1], wv23.y, hv.y);
        }

        // cross-warp partials
#pragma unroll
        for (int i = 0; i < 4; i++) {
            float2 u0 = unp2(acc2[i][0]);
            float2 u1 = unp2(acc2[i][1]);
            *(float4*)(part + ((size_t)warp * 16 + rg * 4 + i) * NB + bg * 4) =
                make_float4(u0.x, u0.y, u1.x, u1.y);
        }
        __syncthreads();

        // reduce + pointwise update for (hj, b_pt)
        float g0 = xg0, g1 = xg1, g2 = xg2, g3 = xg3;
#pragma unroll
        for (int w = 0; w < 4; w++) {
            const float* pr = part + (size_t)w * 16 * NB;
            g0 += pr[(0  + hj) * NB + b_pt];
            g1 += pr[(4  + hj) * NB + b_pt];
            g2 += pr[(8  + hj) * NB + b_pt];
            g3 += pr[(12 + hj) * NB + b_pt];
        }
        float ig = fsig(g0);
        float fg = fsig(g1);
        float gg = ftanh(g2);
        float og = fsig(g3);
        float c_n = fg * c_st + ig * gg;
        float h_n = og * ftanh(c_n);
        if (s < len_b) {
            c_st = c_n; h_st = h_n;
            int t_o = dir ? (len_b - 1 - s) : s;
            out[((size_t)b_pt * Tt + t_o) * HDC + dir * HH + hk] = h_n;
        }
        hwr[hk * NB + b_pt] = h_st;

        // prefetch gate inputs for step s+1 (independent of barrier)
        {
            int sn = s + 1;
            int tx = dir ? (len_b - 1 - sn) : sn;
            if (tx < 0) tx = 0;
            if (tx >= Tt) tx = Tt - 1;
            const float* xp = xg + (size_t)tx * (G4H * NB) + (size_t)hk * NB + b_pt;
            xg0 = __ldg(xp);
            xg1 = __ldg(xp + 256 * NB);
            xg2 = __ldg(xp + 512 * NB);
            xg3 = __ldg(xp + 768 * NB);
        }

        // ---- distributed grid barrier (flag array + gather block) ----
        __threadfence();
        __syncthreads();
        const unsigned gen = (unsigned)s + 1u;
        if (tid == 0) g_arr[(unsigned)blockIdx.x << 5] = gen;
        if (blockIdx.x == 0) {
            if (tid < 32) {
#pragma unroll
                for (int j = 0; j < 4; j++) {
                    volatile unsigned* p = &g_arr[(unsigned)(tid * 4 + j) << 5];
                    while (*p < gen) { }
                }
                __syncwarp();
                if (tid == 0) { __threadfence(); g_rel = gen; }
            }
        } else if (tid == 0) {
            while (g_rel < gen) { }
        }
        __syncthreads();
    }
}

// ---------------- host orchestration ----------------------------------------
extern "C" void kernel_launch(void* const* d_in, const int* in_sizes, int n_in,
                              void* d_out, int out_size) {
    const float* x     = (const float*)d_in[0];
    const int*   xlen  = (const int*)d_in[1];
    const float* Wih1f = (const float*)d_in[2];
    const float* Whh1f = (const float*)d_in[3];
    const float* b1f   = (const float*)d_in[4];
    const float* Wih1b = (const float*)d_in[5];
    const float* Whh1b = (const float*)d_in[6];
    const float* b1b   = (const float*)d_in[7];
    const float* Wih2f = (const float*)d_in[8];
    const float* Whh2f = (const float*)d_in[9];
    const float* b2f   = (const float*)d_in[10];
    const float* Wih2b = (const float*)d_in[11];
    const float* Whh2b = (const float*)d_in[12];
    const float* b2b   = (const float*)d_in[13];
    const float* Wlin  = (const float*)d_in[14];
    const float* blin  = (const float*)d_in[15];
    float* out = (float*)d_out;

    float *xg1f, *xg1b, *xg2f, *xg2b, *out1, *pool1, *out2;
    cudaGetSymbolAddress((void**)&xg1f,  g_xg1f);
    cudaGetSymbolAddress((void**)&xg1b,  g_xg1b);
    cudaGetSymbolAddress((void**)&xg2f,  g_xg2f);
    cudaGetSymbolAddress((void**)&xg2b,  g_xg2b);
    cudaGetSymbolAddress((void**)&out1,  g_out1);
    cudaGetSymbolAddress((void**)&pool1, g_pool1);
    cudaGetSymbolAddress((void**)&out2,  g_out2);

    const long long ot_xg = (long long)G4H * NB;   // xg layout [t][row][b]
    const long long or_xg = NB;
    const long long ob_xg = 1;

    // zero masked-output buffers (graph replays must rewrite every call)
    k_zero<<<4096, 256>>>(out1, (size_t)NB * T1 * HDC);
    k_zero<<<4096, 256>>>(out2, (size_t)NB * T2 * HDC);

    // layer-1 gate projections: M=1024, N=(2000 t x 32 b), K=80
    k_proj<<<dim3(G4H / 256, T1), 128>>>(x, Wih1f, b1f, xg1f, T1, D1, ot_xg, or_xg, ob_xg);
    k_proj<<<dim3(G4H / 256, T1), 128>>>(x, Wih1b, b1b, xg1b, T1, D1, ot_xg, or_xg, ob_xg);

    // layer-1 recurrence
    k_init_rec<<<1, 256>>>();
    k_lstm<<<NBLK, 128>>>(xg1f, xg1b, Whh1f, Whh1b, xlen, 0, out1, T1);

    // max-pool stride 2
    k_pool<<<2048, 256>>>(out1, pool1);

    // layer-2 gate projections: M=1024, K=512
    k_proj<<<dim3(G4H / 256, T2), 128>>>(pool1, Wih2f, b2f, xg2f, T2, HDC, ot_xg, or_xg, ob_xg);
    k_proj<<<dim3(G4H / 256, T2), 128>>>(pool1, Wih2b, b2b, xg2b, T2, HDC, ot_xg, or_xg, ob_xg);

    // layer-2 recurrence (lengths = x_len >> 1)
    k_init_rec<<<1, 256>>>();
    k_lstm<<<NBLK, 128>>>(xg2f, xg2b, Whh2f, Whh2b, xlen, 1, out2, T2);

    // final linear: out[b][t][o] -> M=512, K=512, store-along-row mode
    k_proj<<<dim3(OUTC / 256, T2), 128>>>(out2, Wlin, blin, out, T2, HDC,
                                          (long long)OUTC, 1LL, (long long)T2 * OUTC);

    // lens = x_len // 2 appended as float (second tuple element)
    if (out_size > NB * T2 * OUTC) {
        k_lens<<<1, 32>>>(xlen, out + (size_t)NB * T2 * OUTC);
    }
}

// round 6
// speedup vs baseline: 1.4390x; 1.4390x over previous
#include <cuda_runtime.h>
#include <cuda_bf16.h>
#include <cstdint>
#include <cstddef>
#include <math.h>

#define NB   32      // batch
#define T1   2000    // layer-1 time steps
#define T2   1000    // layer-2 time steps (after pool s=2)
#define D1   80      // input feature dim
#define HH   256     // hidden per direction
#define G4H  1024    // 4*H gate rows
#define HDC  512     // 2*H (bidirectional concat)
#define OUTC 512     // final output channels
#define NBLK 128     // persistent LSTM blocks

typedef unsigned long long ull;

// ---------------- f32x2 packed-FMA helpers (Blackwell FFMA2) -----------------
__device__ __forceinline__ void fma2(ull& d, ull a, ull b) {
    asm("fma.rn.f32x2 %0, %1, %2, %3;" : "=l"(d) : "l"(a), "l"(b), "l"(d));
}
__device__ __forceinline__ ull dup2(float x) {
    ull r; asm("mov.b64 %0, {%1, %1};" : "=l"(r) : "f"(x)); return r;
}
__device__ __forceinline__ float2 unp2(ull v) {
    float2 r; asm("mov.b64 {%0, %1}, %2;" : "=f"(r.x), "=f"(r.y) : "l"(v)); return r;
}

// ---------------- device scratch (static: allocation is forbidden) ----------
__device__ float g_xg1f[(size_t)T1 * G4H * NB];   // [t][gate_row][b]
__device__ float g_xg1b[(size_t)T1 * G4H * NB];
__device__ float g_xg2f[(size_t)T2 * G4H * NB];
__device__ float g_xg2b[(size_t)T2 * G4H * NB];
__device__ float g_out1[(size_t)NB * T1 * HDC];   // [b][t][ch]
__device__ float g_pool1[(size_t)NB * T2 * HDC];
__device__ float g_out2[(size_t)NB * T2 * HDC];
__device__ float g_hbuf[2 * 2 * HH * NB];         // [dir][parity][k][b]
__device__ unsigned g_barCnt;
__device__ volatile unsigned g_barGen;

// ---------------- small helpers ---------------------------------------------
__global__ void k_zero(float* __restrict__ p, size_t n) {
    size_t i = (size_t)blockIdx.x * blockDim.x + threadIdx.x;
    size_t st = (size_t)gridDim.x * blockDim.x;
    for (; i < n; i += st) p[i] = 0.f;
}

__global__ void k_init_rec() {
    for (int j = threadIdx.x; j < 2 * 2 * HH * NB; j += blockDim.x) g_hbuf[j] = 0.f;
    if (threadIdx.x == 0) { g_barCnt = 0u; g_barGen = 0u; }
}

__global__ void k_pool(const float* __restrict__ in, float* __restrict__ out) {
    size_t n = (size_t)NB * T2 * HDC;
    size_t i = (size_t)blockIdx.x * blockDim.x + threadIdx.x;
    size_t st = (size_t)gridDim.x * blockDim.x;
    for (; i < n; i += st) {
        int c  = (int)(i % HDC);
        size_t r = i / HDC;
        int tp = (int)(r % T2);
        int b  = (int)(r / T2);
        const float* p = in + ((size_t)b * T1 + 2 * (size_t)tp) * HDC + c;
        out[i] = fmaxf(p[0], p[HDC]);
    }
}

__global__ void k_lens(const int* __restrict__ xlen, float* __restrict__ out) {
    int i = threadIdx.x;
    if (i < NB) out[i] = (float)(xlen[i] >> 1);
}

// ---------------- projection / linear GEMM (unchanged from R5 — proven) ------
__global__ void __launch_bounds__(128, 2) k_proj(
    const float* __restrict__ X, const float* __restrict__ W,
    const float* __restrict__ bias, float* __restrict__ out,
    int Tt, int K, long long ot, long long orr, long long ob)
{
    __shared__ __align__(16) float a_sh[16][256];   // [k][row]
    __shared__ __align__(16) float b_sh[16][32];    // [k][b]

    const int t    = blockIdx.y;
    const int row0 = blockIdx.x * 256;
    const int tid  = threadIdx.x;
    const int rowg = tid >> 2;   // 0..31 -> rows rowg*8 .. +7
    const int colg = tid & 3;    // 0..3  -> b colg*8 .. +7

    ull acc[4][8];
#pragma unroll
    for (int i = 0; i < 4; i++)
#pragma unroll
        for (int j = 0; j < 8; j++) acc[i][j] = 0ull;

    for (int k0 = 0; k0 < K; k0 += 16) {
        {
            const float* wp = W + (size_t)(row0 + tid) * K + k0;
            float4 v0 = ((const float4*)wp)[0];
            float4 v1 = ((const float4*)wp)[1];
            float4 v2 = ((const float4*)wp)[2];
            float4 v3 = ((const float4*)wp)[3];
            a_sh[ 0][tid] = v0.x; a_sh[ 1][tid] = v0.y; a_sh[ 2][tid] = v0.z; a_sh[ 3][tid] = v0.w;
            a_sh[ 4][tid] = v1.x; a_sh[ 5][tid] = v1.y; a_sh[ 6][tid] = v1.z; a_sh[ 7][tid] = v1.w;
            a_sh[ 8][tid] = v2.x; a_sh[ 9][tid] = v2.y; a_sh[10][tid] = v2.z; a_sh[11][tid] = v2.w;
            a_sh[12][tid] = v3.x; a_sh[13][tid] = v3.y; a_sh[14][tid] = v3.z; a_sh[15][tid] = v3.w;
            wp += (size_t)128 * K;
            v0 = ((const float4*)wp)[0];
            v1 = ((const float4*)wp)[1];
            v2 = ((const float4*)wp)[2];
            v3 = ((const float4*)wp)[3];
            const int r2 = tid + 128;
            a_sh[ 0][r2] = v0.x; a_sh[ 1][r2] = v0.y; a_sh[ 2][r2] = v0.z; a_sh[ 3][r2] = v0.w;
            a_sh[ 4][r2] = v1.x; a_sh[ 5][r2] = v1.y; a_sh[ 6][r2] = v1.z; a_sh[ 7][r2] = v1.w;
            a_sh[ 8][r2] = v2.x; a_sh[ 9][r2] = v2.y; a_sh[10][r2] = v2.z; a_sh[11][r2] = v2.w;
            a_sh[12][r2] = v3.x; a_sh[13][r2] = v3.y; a_sh[14][r2] = v3.z; a_sh[15][r2] = v3.w;
        }
        {
            const int bb = tid >> 2, ko = (tid & 3) * 4;
            const float* xp = X + ((size_t)bb * Tt + t) * K + k0 + ko;
            float4 u = *(const float4*)xp;
            b_sh[ko + 0][bb] = u.x; b_sh[ko + 1][bb] = u.y;
            b_sh[ko + 2][bb] = u.z; b_sh[ko + 3][bb] = u.w;
        }
        __syncthreads();
#pragma unroll
        for (int kk = 0; kk < 16; kk++) {
            ulonglong2 a01 = *(const ulonglong2*)&a_sh[kk][rowg * 8];
            ulonglong2 a23 = *(const ulonglong2*)&a_sh[kk][rowg * 8 + 4];
            float4 u0 = *(const float4*)&b_sh[kk][colg * 8];
            float4 u1 = *(const float4*)&b_sh[kk][colg * 8 + 4];
            ull b0 = dup2(u0.x), b1 = dup2(u0.y), b2 = dup2(u0.z), b3 = dup2(u0.w);
            ull b4 = dup2(u1.x), b5 = dup2(u1.y), b6 = dup2(u1.z), b7 = dup2(u1.w);
            fma2(acc[0][0], a01.x, b0); fma2(acc[0][1], a01.x, b1);
            fma2(acc[0][2], a01.x, b2); fma2(acc[0][3], a01.x, b3);
            fma2(acc[0][4], a01.x, b4); fma2(acc[0][5], a01.x, b5);
            fma2(acc[0][6], a01.x, b6); fma2(acc[0][7], a01.x, b7);
            fma2(acc[1][0], a01.y, b0); fma2(acc[1][1], a01.y, b1);
            fma2(acc[1][2], a01.y, b2); fma2(acc[1][3], a01.y, b3);
            fma2(acc[1][4], a01.y, b4); fma2(acc[1][5], a01.y, b5);
            fma2(acc[1][6], a01.y, b6); fma2(acc[1][7], a01.y, b7);
            fma2(acc[2][0], a23.x, b0); fma2(acc[2][1], a23.x, b1);
            fma2(acc[2][2], a23.x, b2); fma2(acc[2][3], a23.x, b3);
            fma2(acc[2][4], a23.x, b4); fma2(acc[2][5], a23.x, b5);
            fma2(acc[2][6], a23.x, b6); fma2(acc[2][7], a23.x, b7);
            fma2(acc[3][0], a23.y, b0); fma2(acc[3][1], a23.y, b1);
            fma2(acc[3][2], a23.y, b2); fma2(acc[3][3], a23.y, b3);
            fma2(acc[3][4], a23.y, b4); fma2(acc[3][5], a23.y, b5);
            fma2(acc[3][6], a23.y, b6); fma2(acc[3][7], a23.y, b7);
        }
        __syncthreads();
    }

    const int rbase = row0 + rowg * 8;
    float4 bv0 = *(const float4*)&bias[rbase];
    float4 bv1 = *(const float4*)&bias[rbase + 4];
    const float bv[8] = {bv0.x, bv0.y, bv0.z, bv0.w, bv1.x, bv1.y, bv1.z, bv1.w};

    if (ob == 1) {
        float* op = out + (size_t)t * ot + (size_t)rbase * orr + colg * 8;
#pragma unroll
        for (int rp = 0; rp < 4; rp++) {
            float va[8], vb[8];
#pragma unroll
            for (int c = 0; c < 8; c++) {
                float2 u = unp2(acc[rp][c]);
                va[c] = u.x + bv[2 * rp];
                vb[c] = u.y + bv[2 * rp + 1];
            }
            float* r0 = op + (size_t)(2 * rp) * orr;
            float* r1 = op + (size_t)(2 * rp + 1) * orr;
            *(float4*)r0       = make_float4(va[0], va[1], va[2], va[3]);
            *(float4*)(r0 + 4) = make_float4(va[4], va[5], va[6], va[7]);
            *(float4*)r1       = make_float4(vb[0], vb[1], vb[2], vb[3]);
            *(float4*)(r1 + 4) = make_float4(vb[4], vb[5], vb[6], vb[7]);
        }
    } else {
        float* op = out + (size_t)t * ot + rbase;
#pragma unroll
        for (int c = 0; c < 8; c++) {
            size_t boff = (size_t)(colg * 8 + c) * ob;
            float2 p0 = unp2(acc[0][c]);
            float2 p1 = unp2(acc[1][c]);
            float2 p2 = unp2(acc[2][c]);
            float2 p3 = unp2(acc[3][c]);
            *(float4*)(op + boff)     = make_float4(p0.x + bv[0], p0.y + bv[1], p1.x + bv[2], p1.y + bv[3]);
            *(float4*)(op + boff + 4) = make_float4(p2.x + bv[4], p2.y + bv[5], p3.x + bv[6], p3.y + bv[7]);
        }
    }
}

// ---------------- persistent recurrent LSTM (smem-staged h) ------------------
__device__ __forceinline__ float fsig(float x) {
    return 1.f / (1.f + __expf(-x));
}
__device__ __forceinline__ float ftanh(float x) {
    float e = __expf(2.f * x);
    return 1.f - 2.f / (e + 1.f);
}

// dynamic smem layout: w2 (256*16 ull = 32KB) | h_sh (256*32 f = 32KB) | part (8KB)
#define LSTM_SMEM (32768 + 32768 + 8192)

__global__ void __launch_bounds__(128, 1) k_lstm(
    const float* __restrict__ xgF, const float* __restrict__ xgB,
    const float* __restrict__ WhhF, const float* __restrict__ WhhB,
    const int* __restrict__ xlen, int lenShift,
    float* __restrict__ out, int Tt)
{
    extern __shared__ __align__(16) char dynsmem[];
    ull*   w2   = (ull*)dynsmem;                    // [k][rr], duplicated
    float* h_sh = (float*)(dynsmem + 32768);        // [k][b]
    float* part = (float*)(dynsmem + 65536);        // [warp][rr][b]

    const int dir = (int)(blockIdx.x >> 6);
    const int gb  = (int)(blockIdx.x & 63);
    const float* xg  = dir ? xgB : xgF;
    const float* Whh = dir ? WhhB : WhhF;
    float* hb = g_hbuf + dir * (2 * HH * NB);

    const int tid  = threadIdx.x;
    const int warp = tid >> 5, lane = tid & 31;
    const int bg = lane >> 2;     // batch group 0..7
    const int rg = lane & 3;      // gate group 0..3
    const int kbase = warp * 64;  // K section per warp

    // stage Whh slice transposed + duplicated (once)
    {
        const int rr = tid & 15, kp = tid >> 4;    // kp 0..7
        const int grow = (rr >> 2) * HH + gb * 4 + (rr & 3);
        const float* wp = Whh + (size_t)grow * HH + kp * 32;
#pragma unroll
        for (int j = 0; j < 32; j++) w2[(size_t)(kp * 32 + j) * 16 + rr] = dup2(wp[j]);
    }

    const int b_pt = lane;
    const int hj   = warp;
    const int hk   = gb * 4 + hj;
    const int len_b = xlen[b_pt] >> lenShift;
    float c_st = 0.f, h_st = 0.f;

    __syncthreads();

    // gate-input prefetch for step 0
    float xg0, xg1, xg2, xg3;
    {
        int tx = dir ? (len_b - 1) : 0;
        if (tx < 0) tx = 0;
        const float* xp = xg + (size_t)tx * (G4H * NB) + (size_t)hk * NB + b_pt;
        xg0 = __ldg(xp);
        xg1 = __ldg(xp + 256 * NB);
        xg2 = __ldg(xp + 512 * NB);
        xg3 = __ldg(xp + 768 * NB);
    }

    for (int s = 0; s < Tt; s++) {
        const float* hrd = hb + (s & 1) * (HH * NB);
        float* hwr = hb + ((s & 1) ^ 1) * (HH * NB);

        // ---- cooperative stage of h into smem (parallel MLP, L1-bypass) ----
        {
            const float4* src = (const float4*)hrd;
            float4* dst = (float4*)h_sh;
#pragma unroll
            for (int j = 0; j < 16; j++) {
                int idx = j * 128 + tid;
                dst[idx] = __ldcg(src + idx);
            }
        }
        __syncthreads();

        // ---- GEMM slice from smem ----
        ull acc2[4][2] = {};
        const ulonglong2* wp2 = (const ulonglong2*)w2 + (size_t)kbase * 8 + rg * 2;
        const float* hq = h_sh + (size_t)kbase * 32 + bg * 4;
#pragma unroll 8
        for (int k = 0; k < 64; k++) {
            ulonglong2 hv   = *(const ulonglong2*)(hq + (size_t)k * 32);
            ulonglong2 wv01 = wp2[(size_t)k * 8];
            ulonglong2 wv23 = wp2[(size_t)k * 8 + 1];
            fma2(acc2[0][0], wv01.x, hv.x); fma2(acc2[0][1], wv01.x, hv.y);
            fma2(acc2[1][0], wv01.y, hv.x); fma2(acc2[1][1], wv01.y, hv.y);
            fma2(acc2[2][0], wv23.x, hv.x); fma2(acc2[2][1], wv23.x, hv.y);
            fma2(acc2[3][0], wv23.y, hv.x); fma2(acc2[3][1], wv23.y, hv.y);
        }

        // cross-warp partials
#pragma unroll
        for (int i = 0; i < 4; i++) {
            float2 u0 = unp2(acc2[i][0]);
            float2 u1 = unp2(acc2[i][1]);
            *(float4*)(part + ((size_t)warp * 16 + rg * 4 + i) * NB + bg * 4) =
                make_float4(u0.x, u0.y, u1.x, u1.y);
        }
        __syncthreads();

        // reduce + pointwise update for (hj, b_pt)
        float g0 = xg0, g1 = xg1, g2 = xg2, g3 = xg3;
#pragma unroll
        for (int w = 0; w < 4; w++) {
            const float* pr = part + (size_t)w * 16 * NB;
            g0 += pr[(0  + hj) * NB + b_pt];
            g1 += pr[(4  + hj) * NB + b_pt];
            g2 += pr[(8  + hj) * NB + b_pt];
            g3 += pr[(12 + hj) * NB + b_pt];
        }
        float ig = fsig(g0);
        float fg = fsig(g1);
        float gg = ftanh(g2);
        float og = fsig(g3);
        float c_n = fg * c_st + ig * gg;
        float h_n = og * ftanh(c_n);
        if (s < len_b) {
            c_st = c_n; h_st = h_n;
            int t_o = dir ? (len_b - 1 - s) : s;
            out[((size_t)b_pt * Tt + t_o) * HDC + dir * HH + hk] = h_n;
        }
        hwr[hk * NB + b_pt] = h_st;

        // prefetch gate inputs for step s+1 (off the barrier critical path)
        {
            int sn = s + 1;
            int tx = dir ? (len_b - 1 - sn) : sn;
            if (tx < 0) tx = 0;
            if (tx >= Tt) tx = Tt - 1;
            const float* xp = xg + (size_t)tx * (G4H * NB) + (size_t)hk * NB + b_pt;
            xg0 = __ldg(xp);
            xg1 = __ldg(xp + 256 * NB);
            xg2 = __ldg(xp + 512 * NB);
            xg3 = __ldg(xp + 768 * NB);
        }

        // ---- grid barrier (sense-reversal atomic — R3 proven) ----
        __threadfence();
        __syncthreads();
        if (tid == 0) {
            unsigned gen = g_barGen;
            if (atomicAdd(&g_barCnt, 1u) == NBLK - 1u) {
                g_barCnt = 0u;
                __threadfence();
                g_barGen = gen + 1u;
            } else {
                while (g_barGen == gen) { }
            }
        }
        __syncthreads();
    }
}

// ---------------- host orchestration ----------------------------------------
extern "C" void kernel_launch(void* const* d_in, const int* in_sizes, int n_in,
                              void* d_out, int out_size) {
    const float* x     = (const float*)d_in[0];
    const int*   xlen  = (const int*)d_in[1];
    const float* Wih1f = (const float*)d_in[2];
    const float* Whh1f = (const float*)d_in[3];
    const float* b1f   = (const float*)d_in[4];
    const float* Wih1b = (const float*)d_in[5];
    const float* Whh1b = (const float*)d_in[6];
    const float* b1b   = (const float*)d_in[7];
    const float* Wih2f = (const float*)d_in[8];
    const float* Whh2f = (const float*)d_in[9];
    const float* b2f   = (const float*)d_in[10];
    const float* Wih2b = (const float*)d_in[11];
    const float* Whh2b = (const float*)d_in[12];
    const float* b2b   = (const float*)d_in[13];
    const float* Wlin  = (const float*)d_in[14];
    const float* blin  = (const float*)d_in[15];
    float* out = (float*)d_out;

    static bool s_attr_done = false;
    if (!s_attr_done) {
        cudaFuncSetAttribute(k_lstm, cudaFuncAttributeMaxDynamicSharedMemorySize, LSTM_SMEM);
        s_attr_done = true;
    }

    float *xg1f, *xg1b, *xg2f, *xg2b, *out1, *pool1, *out2;
    cudaGetSymbolAddress((void**)&xg1f,  g_xg1f);
    cudaGetSymbolAddress((void**)&xg1b,  g_xg1b);
    cudaGetSymbolAddress((void**)&xg2f,  g_xg2f);
    cudaGetSymbolAddress((void**)&xg2b,  g_xg2b);
    cudaGetSymbolAddress((void**)&out1,  g_out1);
    cudaGetSymbolAddress((void**)&pool1, g_pool1);
    cudaGetSymbolAddress((void**)&out2,  g_out2);

    const long long ot_xg = (long long)G4H * NB;   // xg layout [t][row][b]
    const long long or_xg = NB;
    const long long ob_xg = 1;

    // zero masked-output buffers (graph replays must rewrite every call)
    k_zero<<<4096, 256>>>(out1, (size_t)NB * T1 * HDC);
    k_zero<<<4096, 256>>>(out2, (size_t)NB * T2 * HDC);

    // layer-1 gate projections: M=1024, N=(2000 t x 32 b), K=80
    k_proj<<<dim3(G4H / 256, T1), 128>>>(x, Wih1f, b1f, xg1f, T1, D1, ot_xg, or_xg, ob_xg);
    k_proj<<<dim3(G4H / 256, T1), 128>>>(x, Wih1b, b1b, xg1b, T1, D1, ot_xg, or_xg, ob_xg);

    // layer-1 recurrence
    k_init_rec<<<1, 256>>>();
    k_lstm<<<NBLK, 128, LSTM_SMEM>>>(xg1f, xg1b, Whh1f, Whh1b, xlen, 0, out1, T1);

    // max-pool stride 2
    k_pool<<<2048, 256>>>(out1, pool1);

    // layer-2 gate projections: M=1024, K=512
    k_proj<<<dim3(G4H / 256, T2), 128>>>(pool1, Wih2f, b2f, xg2f, T2, HDC, ot_xg, or_xg, ob_xg);
    k_proj<<<dim3(G4H / 256, T2), 128>>>(pool1, Wih2b, b2b, xg2b, T2, HDC, ot_xg, or_xg, ob_xg);

    // layer-2 recurrence (lengths = x_len >> 1)
    k_init_rec<<<1, 256>>>();
    k_lstm<<<NBLK, 128, LSTM_SMEM>>>(xg2f, xg2b, Whh2f, Whh2b, xlen, 1, out2, T2);

    // final linear: out[b][t][o] -> M=512, K=512, store-along-row mode
    k_proj<<<dim3(OUTC / 256, T2), 128>>>(out2, Wlin, blin, out, T2, HDC,
                                          (long long)OUTC, 1LL, (long long)T2 * OUTC);

    // lens = x_len // 2 appended as float (second tuple element)
    if (out_size > NB * T2 * OUTC) {
        k_lens<<<1, 32>>>(xlen, out + (size_t)NB * T2 * OUTC);
    }
}

// round 7
// speedup vs baseline: 1.4453x; 1.0044x over previous
#include <cuda_runtime.h>
#include <cuda_bf16.h>
#include <cstdint>
#include <cstddef>
#include <math.h>

#define NB   32      // batch
#define T1   2000    // layer-1 time steps
#define T2   1000    // layer-2 time steps (after pool s=2)
#define D1   80      // input feature dim
#define HH   256     // hidden per direction
#define G4H  1024    // 4*H gate rows
#define HDC  512     // 2*H (bidirectional concat)
#define OUTC 512     // final output channels
#define NBLK 128     // persistent LSTM blocks

typedef unsigned long long ull;

// ---------------- f32x2 packed-FMA helpers (Blackwell FFMA2) -----------------
__device__ __forceinline__ void fma2(ull& d, ull a, ull b) {
    asm("fma.rn.f32x2 %0, %1, %2, %3;" : "=l"(d) : "l"(a), "l"(b), "l"(d));
}
__device__ __forceinline__ ull dup2(float x) {
    ull r; asm("mov.b64 %0, {%1, %1};" : "=l"(r) : "f"(x)); return r;
}
__device__ __forceinline__ float2 unp2(ull v) {
    float2 r; asm("mov.b64 {%0, %1}, %2;" : "=f"(r.x), "=f"(r.y) : "l"(v)); return r;
}

// ---------------- device scratch (static: allocation is forbidden) ----------
__device__ float g_xg1f[(size_t)T1 * G4H * NB];   // [t][gate_row][b]
__device__ float g_xg1b[(size_t)T1 * G4H * NB];
__device__ float g_xg2f[(size_t)T2 * G4H * NB];
__device__ float g_xg2b[(size_t)T2 * G4H * NB];
__device__ float g_out1[(size_t)NB * T1 * HDC];   // [b][t][ch]
__device__ float g_pool1[(size_t)NB * T2 * HDC];
__device__ float g_out2[(size_t)NB * T2 * HDC];
__device__ float g_hbuf[2 * 2 * HH * NB];         // [dir][parity][k][b]
// barrier words on SEPARATE 128B lines (atomic line != poll line)
__device__ __align__(128) unsigned g_barCnt[32];
__device__ __align__(128) unsigned g_barGen[32];

// ---------------- small helpers ---------------------------------------------
__global__ void k_zero(float* __restrict__ p, size_t n) {
    size_t i = (size_t)blockIdx.x * blockDim.x + threadIdx.x;
    size_t st = (size_t)gridDim.x * blockDim.x;
    for (; i < n; i += st) p[i] = 0.f;
}

__global__ void k_init_rec() {
    for (int j = threadIdx.x; j < 2 * 2 * HH * NB; j += blockDim.x) g_hbuf[j] = 0.f;
    if (threadIdx.x < 32) { g_barCnt[threadIdx.x] = 0u; g_barGen[threadIdx.x] = 0u; }
}

__global__ void k_pool(const float* __restrict__ in, float* __restrict__ out) {
    size_t n = (size_t)NB * T2 * HDC;
    size_t i = (size_t)blockIdx.x * blockDim.x + threadIdx.x;
    size_t st = (size_t)gridDim.x * blockDim.x;
    for (; i < n; i += st) {
        int c  = (int)(i % HDC);
        size_t r = i / HDC;
        int tp = (int)(r % T2);
        int b  = (int)(r / T2);
        const float* p = in + ((size_t)b * T1 + 2 * (size_t)tp) * HDC + c;
        out[i] = fmaxf(p[0], p[HDC]);
    }
}

__global__ void k_lens(const int* __restrict__ xlen, float* __restrict__ out) {
    int i = threadIdx.x;
    if (i < NB) out[i] = (float)(xlen[i] >> 1);
}

// ---------------- projection / linear GEMM (frozen — proven in R5/R6) --------
__global__ void __launch_bounds__(128, 2) k_proj(
    const float* __restrict__ X, const float* __restrict__ W,
    const float* __restrict__ bias, float* __restrict__ out,
    int Tt, int K, long long ot, long long orr, long long ob)
{
    __shared__ __align__(16) float a_sh[16][256];   // [k][row]
    __shared__ __align__(16) float b_sh[16][32];    // [k][b]

    const int t    = blockIdx.y;
    const int row0 = blockIdx.x * 256;
    const int tid  = threadIdx.x;
    const int rowg = tid >> 2;   // 0..31 -> rows rowg*8 .. +7
    const int colg = tid & 3;    // 0..3  -> b colg*8 .. +7

    ull acc[4][8];
#pragma unroll
    for (int i = 0; i < 4; i++)
#pragma unroll
        for (int j = 0; j < 8; j++) acc[i][j] = 0ull;

    for (int k0 = 0; k0 < K; k0 += 16) {
        {
            const float* wp = W + (size_t)(row0 + tid) * K + k0;
            float4 v0 = ((const float4*)wp)[0];
            float4 v1 = ((const float4*)wp)[1];
            float4 v2 = ((const float4*)wp)[2];
            float4 v3 = ((const float4*)wp)[3];
            a_sh[ 0][tid] = v0.x; a_sh[ 1][tid] = v0.y; a_sh[ 2][tid] = v0.z; a_sh[ 3][tid] = v0.w;
            a_sh[ 4][tid] = v1.x; a_sh[ 5][tid] = v1.y; a_sh[ 6][tid] = v1.z; a_sh[ 7][tid] = v1.w;
            a_sh[ 8][tid] = v2.x; a_sh[ 9][tid] = v2.y; a_sh[10][tid] = v2.z; a_sh[11][tid] = v2.w;
            a_sh[12][tid] = v3.x; a_sh[13][tid] = v3.y; a_sh[14][tid] = v3.z; a_sh[15][tid] = v3.w;
            wp += (size_t)128 * K;
            v0 = ((const float4*)wp)[0];
            v1 = ((const float4*)wp)[1];
            v2 = ((const float4*)wp)[2];
            v3 = ((const float4*)wp)[3];
            const int r2 = tid + 128;
            a_sh[ 0][r2] = v0.x; a_sh[ 1][r2] = v0.y; a_sh[ 2][r2] = v0.z; a_sh[ 3][r2] = v0.w;
            a_sh[ 4][r2] = v1.x; a_sh[ 5][r2] = v1.y; a_sh[ 6][r2] = v1.z; a_sh[ 7][r2] = v1.w;
            a_sh[ 8][r2] = v2.x; a_sh[ 9][r2] = v2.y; a_sh[10][r2] = v2.z; a_sh[11][r2] = v2.w;
            a_sh[12][r2] = v3.x; a_sh[13][r2] = v3.y; a_sh[14][r2] = v3.z; a_sh[15][r2] = v3.w;
        }
        {
            const int bb = tid >> 2, ko = (tid & 3) * 4;
            const float* xp = X + ((size_t)bb * Tt + t) * K + k0 + ko;
            float4 u = *(const float4*)xp;
            b_sh[ko + 0][bb] = u.x; b_sh[ko + 1][bb] = u.y;
            b_sh[ko + 2][bb] = u.z; b_sh[ko + 3][bb] = u.w;
        }
        __syncthreads();
#pragma unroll
        for (int kk = 0; kk < 16; kk++) {
            ulonglong2 a01 = *(const ulonglong2*)&a_sh[kk][rowg * 8];
            ulonglong2 a23 = *(const ulonglong2*)&a_sh[kk][rowg * 8 + 4];
            float4 u0 = *(const float4*)&b_sh[kk][colg * 8];
            float4 u1 = *(const float4*)&b_sh[kk][colg * 8 + 4];
            ull b0 = dup2(u0.x), b1 = dup2(u0.y), b2 = dup2(u0.z), b3 = dup2(u0.w);
            ull b4 = dup2(u1.x), b5 = dup2(u1.y), b6 = dup2(u1.z), b7 = dup2(u1.w);
            fma2(acc[0][0], a01.x, b0); fma2(acc[0][1], a01.x, b1);
            fma2(acc[0][2], a01.x, b2); fma2(acc[0][3], a01.x, b3);
            fma2(acc[0][4], a01.x, b4); fma2(acc[0][5], a01.x, b5);
            fma2(acc[0][6], a01.x, b6); fma2(acc[0][7], a01.x, b7);
            fma2(acc[1][0], a01.y, b0); fma2(acc[1][1], a01.y, b1);
            fma2(acc[1][2], a01.y, b2); fma2(acc[1][3], a01.y, b3);
            fma2(acc[1][4], a01.y, b4); fma2(acc[1][5], a01.y, b5);
            fma2(acc[1][6], a01.y, b6); fma2(acc[1][7], a01.y, b7);
            fma2(acc[2][0], a23.x, b0); fma2(acc[2][1], a23.x, b1);
            fma2(acc[2][2], a23.x, b2); fma2(acc[2][3], a23.x, b3);
            fma2(acc[2][4], a23.x, b4); fma2(acc[2][5], a23.x, b5);
            fma2(acc[2][6], a23.x, b6); fma2(acc[2][7], a23.x, b7);
            fma2(acc[3][0], a23.y, b0); fma2(acc[3][1], a23.y, b1);
            fma2(acc[3][2], a23.y, b2); fma2(acc[3][3], a23.y, b3);
            fma2(acc[3][4], a23.y, b4); fma2(acc[3][5], a23.y, b5);
            fma2(acc[3][6], a23.y, b6); fma2(acc[3][7], a23.y, b7);
        }
        __syncthreads();
    }

    const int rbase = row0 + rowg * 8;
    float4 bv0 = *(const float4*)&bias[rbase];
    float4 bv1 = *(const float4*)&bias[rbase + 4];
    const float bv[8] = {bv0.x, bv0.y, bv0.z, bv0.w, bv1.x, bv1.y, bv1.z, bv1.w};

    if (ob == 1) {
        float* op = out + (size_t)t * ot + (size_t)rbase * orr + colg * 8;
#pragma unroll
        for (int rp = 0; rp < 4; rp++) {
            float va[8], vb[8];
#pragma unroll
            for (int c = 0; c < 8; c++) {
                float2 u = unp2(acc[rp][c]);
                va[c] = u.x + bv[2 * rp];
                vb[c] = u.y + bv[2 * rp + 1];
            }
            float* r0 = op + (size_t)(2 * rp) * orr;
            float* r1 = op + (size_t)(2 * rp + 1) * orr;
            *(float4*)r0       = make_float4(va[0], va[1], va[2], va[3]);
            *(float4*)(r0 + 4) = make_float4(va[4], va[5], va[6], va[7]);
            *(float4*)r1       = make_float4(vb[0], vb[1], vb[2], vb[3]);
            *(float4*)(r1 + 4) = make_float4(vb[4], vb[5], vb[6], vb[7]);
        }
    } else {
        float* op = out + (size_t)t * ot + rbase;
#pragma unroll
        for (int c = 0; c < 8; c++) {
            size_t boff = (size_t)(colg * 8 + c) * ob;
            float2 p0 = unp2(acc[0][c]);
            float2 p1 = unp2(acc[1][c]);
            float2 p2 = unp2(acc[2][c]);
            float2 p3 = unp2(acc[3][c]);
            *(float4*)(op + boff)     = make_float4(p0.x + bv[0], p0.y + bv[1], p1.x + bv[2], p1.y + bv[3]);
            *(float4*)(op + boff + 4) = make_float4(p2.x + bv[4], p2.y + bv[5], p3.x + bv[6], p3.y + bv[7]);
        }
    }
}

// ---------------- persistent recurrent LSTM (smem-staged h) ------------------
__device__ __forceinline__ float fsig(float x) {
    return 1.f / (1.f + __expf(-x));
}
__device__ __forceinline__ float ftanh(float x) {
    float e = __expf(2.f * x);
    return 1.f - 2.f / (e + 1.f);
}

// dynamic smem layout: w2 (256*16 ull = 32KB) | h_sh (256*32 f = 32KB) | part (8KB)
#define LSTM_SMEM (32768 + 32768 + 8192)

__global__ void __launch_bounds__(128, 1) k_lstm(
    const float* __restrict__ xgF, const float* __restrict__ xgB,
    const float* __restrict__ WhhF, const float* __restrict__ WhhB,
    const int* __restrict__ xlen, int lenShift,
    float* __restrict__ out, int Tt)
{
    extern __shared__ __align__(16) char dynsmem[];
    ull*   w2   = (ull*)dynsmem;                    // [k][rr], duplicated
    float* h_sh = (float*)(dynsmem + 32768);        // [k][b]
    float* part = (float*)(dynsmem + 65536);        // [warp][rr][b]

    const int dir = (int)(blockIdx.x >> 6);
    const int gb  = (int)(blockIdx.x & 63);
    const float* xg  = dir ? xgB : xgF;
    const float* Whh = dir ? WhhB : WhhF;
    float* hb = g_hbuf + dir * (2 * HH * NB);

    const int tid  = threadIdx.x;
    const int warp = tid >> 5, lane = tid & 31;
    const int bg = lane >> 2;     // batch group 0..7
    const int rg = lane & 3;      // gate group 0..3
    const int kbase = warp * 64;  // K section per warp

    // stage Whh slice transposed + duplicated (once)
    {
        const int rr = tid & 15, kp = tid >> 4;    // kp 0..7
        const int grow = (rr >> 2) * HH + gb * 4 + (rr & 3);
        const float* wp = Whh + (size_t)grow * HH + kp * 32;
#pragma unroll
        for (int j = 0; j < 32; j++) w2[(size_t)(kp * 32 + j) * 16 + rr] = dup2(wp[j]);
    }

    const int b_pt = lane;
    const int hj   = warp;
    const int hk   = gb * 4 + hj;
    const int len_b = xlen[b_pt] >> lenShift;
    float c_st = 0.f, h_st = 0.f;

    unsigned* barCnt = &g_barCnt[0];
    unsigned* barGen = &g_barGen[0];

    __syncthreads();

    // gate-input prefetch for step 0
    float xg0, xg1, xg2, xg3;
    {
        int tx = dir ? (len_b - 1) : 0;
        if (tx < 0) tx = 0;
        const float* xp = xg + (size_t)tx * (G4H * NB) + (size_t)hk * NB + b_pt;
        xg0 = __ldg(xp);
        xg1 = __ldg(xp + 256 * NB);
        xg2 = __ldg(xp + 512 * NB);
        xg3 = __ldg(xp + 768 * NB);
    }

    for (int s = 0; s < Tt; s++) {
        const float* hrd = hb + (s & 1) * (HH * NB);
        float* hwr = hb + ((s & 1) ^ 1) * (HH * NB);

        // ---- cooperative stage of h into smem (parallel MLP, L1-bypass) ----
        {
            const float4* src = (const float4*)hrd;
            float4* dst = (float4*)h_sh;
#pragma unroll
            for (int j = 0; j < 16; j++) {
                int idx = j * 128 + tid;
                dst[idx] = __ldcg(src + idx);
            }
        }
        __syncthreads();

        // ---- GEMM slice from smem ----
        ull acc2[4][2] = {};
        const ulonglong2* wp2 = (const ulonglong2*)w2 + (size_t)kbase * 8 + rg * 2;
        const float* hq = h_sh + (size_t)kbase * 32 + bg * 4;
#pragma unroll 8
        for (int k = 0; k < 64; k++) {
            ulonglong2 hv   = *(const ulonglong2*)(hq + (size_t)k * 32);
            ulonglong2 wv01 = wp2[(size_t)k * 8];
            ulonglong2 wv23 = wp2[(size_t)k * 8 + 1];
            fma2(acc2[0][0], wv01.x, hv.x); fma2(acc2[0][1], wv01.x, hv.y);
            fma2(acc2[1][0], wv01.y, hv.x); fma2(acc2[1][1], wv01.y, hv.y);
            fma2(acc2[2][0], wv23.x, hv.x); fma2(acc2[2][1], wv23.x, hv.y);
            fma2(acc2[3][0], wv23.y, hv.x); fma2(acc2[3][1], wv23.y, hv.y);
        }

        // cross-warp partials
#pragma unroll
        for (int i = 0; i < 4; i++) {
            float2 u0 = unp2(acc2[i][0]);
            float2 u1 = unp2(acc2[i][1]);
            *(float4*)(part + ((size_t)warp * 16 + rg * 4 + i) * NB + bg * 4) =
                make_float4(u0.x, u0.y, u1.x, u1.y);
        }
        __syncthreads();

        // reduce + pointwise update for (hj, b_pt)
        float g0 = xg0, g1 = xg1, g2 = xg2, g3 = xg3;
#pragma unroll
        for (int w = 0; w < 4; w++) {
            const float* pr = part + (size_t)w * 16 * NB;
            g0 += pr[(0  + hj) * NB + b_pt];
            g1 += pr[(4  + hj) * NB + b_pt];
            g2 += pr[(8  + hj) * NB + b_pt];
            g3 += pr[(12 + hj) * NB + b_pt];
        }
        float ig = fsig(g0);
        float fg = fsig(g1);
        float gg = ftanh(g2);
        float og = fsig(g3);
        float c_n = fg * c_st + ig * gg;
        float h_n = og * ftanh(c_n);
        if (s < len_b) {
            c_st = c_n; h_st = h_n;
            int t_o = dir ? (len_b - 1 - s) : s;
            out[((size_t)b_pt * Tt + t_o) * HDC + dir * HH + hk] = h_n;
        }
        // h-state write straight to L2 (coherence point for next step's __ldcg)
        __stcg(&hwr[hk * NB + b_pt], h_st);

        // prefetch gate inputs for step s+1 (off the barrier critical path)
        {
            int sn = s + 1;
            int tx = dir ? (len_b - 1 - sn) : sn;
            if (tx < 0) tx = 0;
            if (tx >= Tt) tx = Tt - 1;
            const float* xp = xg + (size_t)tx * (G4H * NB) + (size_t)hk * NB + b_pt;
            xg0 = __ldg(xp);
            xg1 = __ldg(xp + 256 * NB);
            xg2 = __ldg(xp + 512 * NB);
            xg3 = __ldg(xp + 768 * NB);
        }

        // ---- grid barrier: acq_rel arrive + acquire poll (no MEMBAR) ----
        __syncthreads();     // all h-stores of this block issued before arrive
        if (tid == 0) {
            const unsigned target = (unsigned)s + 1u;
            unsigned old;
            asm volatile("atom.acq_rel.gpu.global.add.u32 %0, [%1], %2;"
                         : "=r"(old) : "l"(barCnt), "r"(1u) : "memory");
            if (old == NBLK - 1u) {
                asm volatile("st.relaxed.gpu.global.u32 [%0], %1;"
                             :: "l"(barCnt), "r"(0u) : "memory");
                asm volatile("st.release.gpu.global.u32 [%0], %1;"
                             :: "l"(barGen), "r"(target) : "memory");
            } else {
                unsigned g;
                do {
                    asm volatile("ld.acquire.gpu.global.u32 %0, [%1];"
                                 : "=r"(g) : "l"(barGen) : "memory");
                } while (g < target);
            }
        }
        __syncthreads();
    }
}

// ---------------- host orchestration ----------------------------------------
extern "C" void kernel_launch(void* const* d_in, const int* in_sizes, int n_in,
                              void* d_out, int out_size) {
    const float* x     = (const float*)d_in[0];
    const int*   xlen  = (const int*)d_in[1];
    const float* Wih1f = (const float*)d_in[2];
    const float* Whh1f = (const float*)d_in[3];
    const float* b1f   = (const float*)d_in[4];
    const float* Wih1b = (const float*)d_in[5];
    const float* Whh1b = (const float*)d_in[6];
    const float* b1b   = (const float*)d_in[7];
    const float* Wih2f = (const float*)d_in[8];
    const float* Whh2f = (const float*)d_in[9];
    const float* b2f   = (const float*)d_in[10];
    const float* Wih2b = (const float*)d_in[11];
    const float* Whh2b = (const float*)d_in[12];
    const float* b2b   = (const float*)d_in[13];
    const float* Wlin  = (const float*)d_in[14];
    const float* blin  = (const float*)d_in[15];
    float* out = (float*)d_out;

    static bool s_attr_done = false;
    if (!s_attr_done) {
        cudaFuncSetAttribute(k_lstm, cudaFuncAttributeMaxDynamicSharedMemorySize, LSTM_SMEM);
        s_attr_done = true;
    }

    float *xg1f, *xg1b, *xg2f, *xg2b, *out1, *pool1, *out2;
    cudaGetSymbolAddress((void**)&xg1f,  g_xg1f);
    cudaGetSymbolAddress((void**)&xg1b,  g_xg1b);
    cudaGetSymbolAddress((void**)&xg2f,  g_xg2f);
    cudaGetSymbolAddress((void**)&xg2b,  g_xg2b);
    cudaGetSymbolAddress((void**)&out1,  g_out1);
    cudaGetSymbolAddress((void**)&pool1, g_pool1);
    cudaGetSymbolAddress((void**)&out2,  g_out2);

    const long long ot_xg = (long long)G4H * NB;   // xg layout [t][row][b]
    const long long or_xg = NB;
    const long long ob_xg = 1;

    // zero masked-output buffers (graph replays must rewrite every call)
    k_zero<<<4096, 256>>>(out1, (size_t)NB * T1 * HDC);
    k_zero<<<4096, 256>>>(out2, (size_t)NB * T2 * HDC);

    // layer-1 gate projections: M=1024, N=(2000 t x 32 b), K=80
    k_proj<<<dim3(G4H / 256, T1), 128>>>(x, Wih1f, b1f, xg1f, T1, D1, ot_xg, or_xg, ob_xg);
    k_proj<<<dim3(G4H / 256, T1), 128>>>(x, Wih1b, b1b, xg1b, T1, D1, ot_xg, or_xg, ob_xg);

    // layer-1 recurrence
    k_init_rec<<<1, 256>>>();
    k_lstm<<<NBLK, 128, LSTM_SMEM>>>(xg1f, xg1b, Whh1f, Whh1b, xlen, 0, out1, T1);

    // max-pool stride 2
    k_pool<<<2048, 256>>>(out1, pool1);

    // layer-2 gate projections: M=1024, K=512
    k_proj<<<dim3(G4H / 256, T2), 128>>>(pool1, Wih2f, b2f, xg2f, T2, HDC, ot_xg, or_xg, ob_xg);
    k_proj<<<dim3(G4H / 256, T2), 128>>>(pool1, Wih2b, b2b, xg2b, T2, HDC, ot_xg, or_xg, ob_xg);

    // layer-2 recurrence (lengths = x_len >> 1)
    k_init_rec<<<1, 256>>>();
    k_lstm<<<NBLK, 128, LSTM_SMEM>>>(xg2f, xg2b, Whh2f, Whh2b, xlen, 1, out2, T2);

    // final linear: out[b][t][o] -> M=512, K=512, store-along-row mode
    k_proj<<<dim3(OUTC / 256, T2), 128>>>(out2, Wlin, blin, out, T2, HDC,
                                          (long long)OUTC, 1LL, (long long)T2 * OUTC);

    // lens = x_len // 2 appended as float (second tuple element)
    if (out_size > NB * T2 * OUTC) {
        k_lens<<<1, 32>>>(xlen, out + (size_t)NB * T2 * OUTC);
    }
}

// round 8
// speedup vs baseline: 1.9079x; 1.3201x over previous
#include <cuda_runtime.h>
#include <cuda_bf16.h>
#include <cstdint>
#include <cstddef>
#include <math.h>

#define NB   32      // batch
#define T1   2000
#define T2   1000
#define D1   80
#define HH   256     // hidden per direction
#define G4H  1024    // 4*H gate rows
#define HDC  512
#define OUTC 512
#define NGRP 8       // 2 dirs x 4 batch-shards
#define GRPB 16      // blocks per group (h-shards)

typedef unsigned long long ull;

// ---------------- f32x2 packed-FMA helpers (Blackwell FFMA2) -----------------
__device__ __forceinline__ void fma2(ull& d, ull a, ull b) {
    asm("fma.rn.f32x2 %0, %1, %2, %3;" : "=l"(d) : "l"(a), "l"(b), "l"(d));
}
__device__ __forceinline__ ull dup2(float x) {
    ull r; asm("mov.b64 %0, {%1, %1};" : "=l"(r) : "f"(x)); return r;
}
__device__ __forceinline__ float2 unp2(ull v) {
    float2 r; asm("mov.b64 {%0, %1}, %2;" : "=f"(r.x), "=f"(r.y) : "l"(v)); return r;
}

// ---------------- device scratch ---------------------------------------------
__device__ float g_xg1f[(size_t)T1 * G4H * NB];   // [t][gate_row][b]
__device__ float g_xg1b[(size_t)T1 * G4H * NB];
__device__ float g_xg2f[(size_t)T2 * G4H * NB];
__device__ float g_xg2b[(size_t)T2 * G4H * NB];
__device__ float g_out1[(size_t)NB * T1 * HDC];   // [b][t][ch]
__device__ float g_pool1[(size_t)NB * T2 * HDC];
__device__ float g_out2[(size_t)NB * T2 * HDC];
// h exchange: [group(8)][parity(2)][k(256)][b(8)]
__device__ float g_hbuf2[NGRP * 2 * HH * 8];
__device__ __align__(128) unsigned g_barCnt[NGRP * 32];
__device__ __align__(128) unsigned g_barGen[NGRP * 32];

// ---------------- small helpers ---------------------------------------------
__global__ void k_zero(float* __restrict__ p, size_t n) {
    size_t i = (size_t)blockIdx.x * blockDim.x + threadIdx.x;
    size_t st = (size_t)gridDim.x * blockDim.x;
    for (; i < n; i += st) p[i] = 0.f;
}

__global__ void k_init_rec() {
    for (int j = threadIdx.x; j < NGRP * 2 * HH * 8; j += blockDim.x) g_hbuf2[j] = 0.f;
    if (threadIdx.x < NGRP * 32) { g_barCnt[threadIdx.x] = 0u; g_barGen[threadIdx.x] = 0u; }
}

__global__ void k_pool(const float* __restrict__ in, float* __restrict__ out) {
    size_t n = (size_t)NB * T2 * HDC;
    size_t i = (size_t)blockIdx.x * blockDim.x + threadIdx.x;
    size_t st = (size_t)gridDim.x * blockDim.x;
    for (; i < n; i += st) {
        int c  = (int)(i % HDC);
        size_t r = i / HDC;
        int tp = (int)(r % T2);
        int b  = (int)(r / T2);
        const float* p = in + ((size_t)b * T1 + 2 * (size_t)tp) * HDC + c;
        out[i] = fmaxf(p[0], p[HDC]);
    }
}

__global__ void k_lens(const int* __restrict__ xlen, float* __restrict__ out) {
    int i = threadIdx.x;
    if (i < NB) out[i] = (float)(xlen[i] >> 1);
}

// ---------------- projection / linear GEMM (frozen — proven) -----------------
__global__ void __launch_bounds__(128, 2) k_proj(
    const float* __restrict__ X, const float* __restrict__ W,
    const float* __restrict__ bias, float* __restrict__ out,
    int Tt, int K, long long ot, long long orr, long long ob)
{
    __shared__ __align__(16) float a_sh[16][256];
    __shared__ __align__(16) float b_sh[16][32];

    const int t    = blockIdx.y;
    const int row0 = blockIdx.x * 256;
    const int tid  = threadIdx.x;
    const int rowg = tid >> 2;
    const int colg = tid & 3;

    ull acc[4][8];
#pragma unroll
    for (int i = 0; i < 4; i++)
#pragma unroll
        for (int j = 0; j < 8; j++) acc[i][j] = 0ull;

    for (int k0 = 0; k0 < K; k0 += 16) {
        {
            const float* wp = W + (size_t)(row0 + tid) * K + k0;
            float4 v0 = ((const float4*)wp)[0];
            float4 v1 = ((const float4*)wp)[1];
            float4 v2 = ((const float4*)wp)[2];
            float4 v3 = ((const float4*)wp)[3];
            a_sh[ 0][tid] = v0.x; a_sh[ 1][tid] = v0.y; a_sh[ 2][tid] = v0.z; a_sh[ 3][tid] = v0.w;
            a_sh[ 4][tid] = v1.x; a_sh[ 5][tid] = v1.y; a_sh[ 6][tid] = v1.z; a_sh[ 7][tid] = v1.w;
            a_sh[ 8][tid] = v2.x; a_sh[ 9][tid] = v2.y; a_sh[10][tid] = v2.z; a_sh[11][tid] = v2.w;
            a_sh[12][tid] = v3.x; a_sh[13][tid] = v3.y; a_sh[14][tid] = v3.z; a_sh[15][tid] = v3.w;
            wp += (size_t)128 * K;
            v0 = ((const float4*)wp)[0];
            v1 = ((const float4*)wp)[1];
            v2 = ((const float4*)wp)[2];
            v3 = ((const float4*)wp)[3];
            const int r2 = tid + 128;
            a_sh[ 0][r2] = v0.x; a_sh[ 1][r2] = v0.y; a_sh[ 2][r2] = v0.z; a_sh[ 3][r2] = v0.w;
            a_sh[ 4][r2] = v1.x; a_sh[ 5][r2] = v1.y; a_sh[ 6][r2] = v1.z; a_sh[ 7][r2] = v1.w;
            a_sh[ 8][r2] = v2.x; a_sh[ 9][r2] = v2.y; a_sh[10][r2] = v2.z; a_sh[11][r2] = v2.w;
            a_sh[12][r2] = v3.x; a_sh[13][r2] = v3.y; a_sh[14][r2] = v3.z; a_sh[15][r2] = v3.w;
        }
        {
            const int bb = tid >> 2, ko = (tid & 3) * 4;
            const float* xp = X + ((size_t)bb * Tt + t) * K + k0 + ko;
            float4 u = *(const float4*)xp;
            b_sh[ko + 0][bb] = u.x; b_sh[ko + 1][bb] = u.y;
            b_sh[ko + 2][bb] = u.z; b_sh[ko + 3][bb] = u.w;
        }
        __syncthreads();
#pragma unroll
        for (int kk = 0; kk < 16; kk++) {
            ulonglong2 a01 = *(const ulonglong2*)&a_sh[kk][rowg * 8];
            ulonglong2 a23 = *(const ulonglong2*)&a_sh[kk][rowg * 8 + 4];
            float4 u0 = *(const float4*)&b_sh[kk][colg * 8];
            float4 u1 = *(const float4*)&b_sh[kk][colg * 8 + 4];
            ull b0 = dup2(u0.x), b1 = dup2(u0.y), b2 = dup2(u0.z), b3 = dup2(u0.w);
            ull b4 = dup2(u1.x), b5 = dup2(u1.y), b6 = dup2(u1.z), b7 = dup2(u1.w);
            fma2(acc[0][0], a01.x, b0); fma2(acc[0][1], a01.x, b1);
            fma2(acc[0][2], a01.x, b2); fma2(acc[0][3], a01.x, b3);
            fma2(acc[0][4], a01.x, b4); fma2(acc[0][5], a01.x, b5);
            fma2(acc[0][6], a01.x, b6); fma2(acc[0][7], a01.x, b7);
            fma2(acc[1][0], a01.y, b0); fma2(acc[1][1], a01.y, b1);
            fma2(acc[1][2], a01.y, b2); fma2(acc[1][3], a01.y, b3);
            fma2(acc[1][4], a01.y, b4); fma2(acc[1][5], a01.y, b5);
            fma2(acc[1][6], a01.y, b6); fma2(acc[1][7], a01.y, b7);
            fma2(acc[2][0], a23.x, b0); fma2(acc[2][1], a23.x, b1);
            fma2(acc[2][2], a23.x, b2); fma2(acc[2][3], a23.x, b3);
            fma2(acc[2][4], a23.x, b4); fma2(acc[2][5], a23.x, b5);
            fma2(acc[2][6], a23.x, b6); fma2(acc[2][7], a23.x, b7);
            fma2(acc[3][0], a23.y, b0); fma2(acc[3][1], a23.y, b1);
            fma2(acc[3][2], a23.y, b2); fma2(acc[3][3], a23.y, b3);
            fma2(acc[3][4], a23.y, b4); fma2(acc[3][5], a23.y, b5);
            fma2(acc[3][6], a23.y, b6); fma2(acc[3][7], a23.y, b7);
        }
        __syncthreads();
    }

    const int rbase = row0 + rowg * 8;
    float4 bv0 = *(const float4*)&bias[rbase];
    float4 bv1 = *(const float4*)&bias[rbase + 4];
    const float bv[8] = {bv0.x, bv0.y, bv0.z, bv0.w, bv1.x, bv1.y, bv1.z, bv1.w};

    if (ob == 1) {
        float* op = out + (size_t)t * ot + (size_t)rbase * orr + colg * 8;
#pragma unroll
        for (int rp = 0; rp < 4; rp++) {
            float va[8], vb[8];
#pragma unroll
            for (int c = 0; c < 8; c++) {
                float2 u = unp2(acc[rp][c]);
                va[c] = u.x + bv[2 * rp];
                vb[c] = u.y + bv[2 * rp + 1];
            }
            float* r0 = op + (size_t)(2 * rp) * orr;
            float* r1 = op + (size_t)(2 * rp + 1) * orr;
            *(float4*)r0       = make_float4(va[0], va[1], va[2], va[3]);
            *(float4*)(r0 + 4) = make_float4(va[4], va[5], va[6], va[7]);
            *(float4*)r1       = make_float4(vb[0], vb[1], vb[2], vb[3]);
            *(float4*)(r1 + 4) = make_float4(vb[4], vb[5], vb[6], vb[7]);
        }
    } else {
        float* op = out + (size_t)t * ot + rbase;
#pragma unroll
        for (int c = 0; c < 8; c++) {
            size_t boff = (size_t)(colg * 8 + c) * ob;
            float2 p0 = unp2(acc[0][c]);
            float2 p1 = unp2(acc[1][c]);
            float2 p2 = unp2(acc[2][c]);
            float2 p3 = unp2(acc[3][c]);
            *(float4*)(op + boff)     = make_float4(p0.x + bv[0], p0.y + bv[1], p1.x + bv[2], p1.y + bv[3]);
            *(float4*)(op + boff + 4) = make_float4(p2.x + bv[4], p2.y + bv[5], p3.x + bv[6], p3.y + bv[7]);
        }
    }
}

// ---------------- persistent recurrent LSTM: batch-sharded groups ------------
__device__ __forceinline__ float fsig(float x) {
    return 1.f / (1.f + __expf(-x));
}
__device__ __forceinline__ float ftanh(float x) {
    float e = __expf(2.f * x);
    return 1.f - 2.f / (e + 1.f);
}

// smem: w_sh 64KB [k(256)][row(64)] | h_sh 8KB [k(256)][b(8)] | part [4][64][9]
#define PART_STRIDE 9
#define LSTM_SMEM (65536 + 8192 + 4 * 64 * PART_STRIDE * 4)

__global__ void __launch_bounds__(128, 1) k_lstm(
    const float* __restrict__ xgF, const float* __restrict__ xgB,
    const float* __restrict__ WhhF, const float* __restrict__ WhhB,
    const int* __restrict__ xlen, int lenShift,
    float* __restrict__ out, int Tt)
{
    extern __shared__ __align__(16) char dynsmem[];
    float* w_sh = (float*)dynsmem;                   // [256][64]
    float* h_sh = (float*)(dynsmem + 65536);         // [256][8]
    float* part = (float*)(dynsmem + 65536 + 8192);  // [4][64][9]

    const int bx  = (int)blockIdx.x;
    const int dir = bx >> 6;           // 0 fwd, 1 bwd
    const int bs  = (bx >> 4) & 3;     // batch shard (8 batches)
    const int hs  = bx & 15;           // h shard (16 h)
    const int gid = dir * 4 + bs;      // group 0..7

    const float* xg  = dir ? xgB : xgF;
    const float* Whh = dir ? WhhB : WhhF;
    float* hbase = g_hbuf2 + (size_t)gid * (2 * HH * 8);

    const int tid  = threadIdx.x;
    const int warp = tid >> 5, lane = tid & 31;
    const int q    = lane & 15;        // row quad (4 rows)
    const int bg4  = lane >> 4;        // batch group of 4 (0,1)
    const int kbase = warp * 64;

    // ---- one-time: stage Whh slice [256 k][64 local rows] ----
    // local row r = g*16 + h_local  ->  global row g*256 + hs*16 + h_local
    {
        const int r  = tid & 63;
        const int ko = (tid >> 6) * 128;
        const int grow = (r >> 4) * HH + hs * 16 + (r & 15);
        const float* wp = Whh + (size_t)grow * HH + ko;
#pragma unroll
        for (int j = 0; j < 128; j += 4) {
            float4 v = *(const float4*)(wp + j);
            w_sh[(size_t)(ko + j + 0) * 64 + r] = v.x;
            w_sh[(size_t)(ko + j + 1) * 64 + r] = v.y;
            w_sh[(size_t)(ko + j + 2) * 64 + r] = v.z;
            w_sh[(size_t)(ko + j + 3) * 64 + r] = v.w;
        }
    }

    // ---- pointwise role: thread owns (h_local, b_local) ----
    const int hl_p = tid >> 3;             // 0..15
    const int bl_p = tid & 7;              // 0..7
    const int hk   = hs * 16 + hl_p;       // global h index
    const int b_g  = bs * 8 + bl_p;        // global batch
    const int len_b = xlen[b_g] >> lenShift;
    int gmax = 0;
#pragma unroll
    for (int j = 0; j < 8; j++) {
        int l = xlen[bs * 8 + j] >> lenShift;
        gmax = (l > gmax) ? l : gmax;
    }
    float c_st = 0.f, h_st = 0.f;

    unsigned* barCnt = &g_barCnt[gid * 32];
    unsigned* barGen = &g_barGen[gid * 32];

    __syncthreads();

    // gate-input prefetch for step 0
    float xg0, xg1, xg2, xg3;
    {
        int tx = dir ? (len_b - 1) : 0;
        if (tx < 0) tx = 0;
        const float* xp = xg + (size_t)tx * (G4H * NB) + (size_t)hk * NB + b_g;
        xg0 = __ldg(xp);
        xg1 = __ldg(xp + 256 * NB);
        xg2 = __ldg(xp + 512 * NB);
        xg3 = __ldg(xp + 768 * NB);
    }

    for (int s = 0; s < gmax; s++) {
        const float* hrd = hbase + (s & 1) * (HH * 8);
        float* hwr = hbase + ((s & 1) ^ 1) * (HH * 8);

        // ---- stage h (8KB) into smem ----
        {
            const float4* src = (const float4*)hrd;
            float4* dst = (float4*)h_sh;
#pragma unroll
            for (int j = 0; j < 4; j++) {
                int idx = j * 128 + tid;
                dst[idx] = __ldcg(src + idx);
            }
        }
        __syncthreads();

        // ---- GEMM slice: rows q*4..+3 (2 f32x2 pairs) x batches bg4*4..+3 ----
        ull acc[2][4] = {};
        const float* wq = w_sh + (size_t)kbase * 64 + q * 4;
        const float* hq = h_sh + (size_t)kbase * 8 + bg4 * 4;
#pragma unroll 16
        for (int k = 0; k < 64; k++) {
            ulonglong2 wv = *(const ulonglong2*)(wq + (size_t)k * 64);
            float4 hv = *(const float4*)(hq + (size_t)k * 8);
            ull h0 = dup2(hv.x), h1 = dup2(hv.y), h2 = dup2(hv.z), h3 = dup2(hv.w);
            fma2(acc[0][0], wv.x, h0); fma2(acc[0][1], wv.x, h1);
            fma2(acc[0][2], wv.x, h2); fma2(acc[0][3], wv.x, h3);
            fma2(acc[1][0], wv.y, h0); fma2(acc[1][1], wv.y, h1);
            fma2(acc[1][2], wv.y, h2); fma2(acc[1][3], wv.y, h3);
        }

        // ---- partials: part[warp][row(64)][b(8)] stride 9 (scalar stores) ----
#pragma unroll
        for (int i = 0; i < 2; i++) {
#pragma unroll
            for (int j = 0; j < 4; j++) {
                float2 u = unp2(acc[i][j]);
                float* p0 = part + ((size_t)warp * 64 + q * 4 + 2 * i) * PART_STRIDE + bg4 * 4 + j;
                p0[0] = u.x;
                p0[PART_STRIDE] = u.y;
            }
        }
        __syncthreads();

        // ---- reduce + pointwise for (hl_p, bl_p) ----
        float g0 = xg0, g1 = xg1, g2 = xg2, g3 = xg3;
#pragma unroll
        for (int w = 0; w < 4; w++) {
            const float* pr = part + (size_t)w * 64 * PART_STRIDE + bl_p;
            g0 += pr[(0  + hl_p) * PART_STRIDE];
            g1 += pr[(16 + hl_p) * PART_STRIDE];
            g2 += pr[(32 + hl_p) * PART_STRIDE];
            g3 += pr[(48 + hl_p) * PART_STRIDE];
        }
        float ig = fsig(g0);
        float fg = fsig(g1);
        float gg = ftanh(g2);
        float og = fsig(g3);
        float c_n = fg * c_st + ig * gg;
        float h_n = og * ftanh(c_n);
        if (s < len_b) {
            c_st = c_n; h_st = h_n;
            int t_o = dir ? (len_b - 1 - s) : s;
            out[((size_t)b_g * Tt + t_o) * HDC + dir * HH + hk] = h_n;
        }
        __stcg(&hwr[hk * 8 + bl_p], h_st);

        // prefetch gate inputs for step s+1
        {
            int sn = s + 1;
            int tx = dir ? (len_b - 1 - sn) : sn;
            if (tx < 0) tx = 0;
            if (tx >= Tt) tx = Tt - 1;
            const float* xp = xg + (size_t)tx * (G4H * NB) + (size_t)hk * NB + b_g;
            xg0 = __ldg(xp);
            xg1 = __ldg(xp + 256 * NB);
            xg2 = __ldg(xp + 512 * NB);
            xg3 = __ldg(xp + 768 * NB);
        }

        // ---- group barrier (16 blocks, private lines) ----
        __syncthreads();
        if (tid == 0) {
            const unsigned target = (unsigned)s + 1u;
            unsigned old;
            asm volatile("atom.acq_rel.gpu.global.add.u32 %0, [%1], %2;"
                         : "=r"(old) : "l"(barCnt), "r"(1u) : "memory");
            if (old == GRPB - 1u) {
                asm volatile("st.relaxed.gpu.global.u32 [%0], %1;"
                             :: "l"(barCnt), "r"(0u) : "memory");
                asm volatile("st.release.gpu.global.u32 [%0], %1;"
                             :: "l"(barGen), "r"(target) : "memory");
            } else {
                unsigned g;
                do {
                    asm volatile("ld.acquire.gpu.global.u32 %0, [%1];"
                                 : "=r"(g) : "l"(barGen) : "memory");
                } while (g < target);
            }
        }
        __syncthreads();
    }
}

// ---------------- host orchestration ----------------------------------------
extern "C" void kernel_launch(void* const* d_in, const int* in_sizes, int n_in,
                              void* d_out, int out_size) {
    const float* x     = (const float*)d_in[0];
    const int*   xlen  = (const int*)d_in[1];
    const float* Wih1f = (const float*)d_in[2];
    const float* Whh1f = (const float*)d_in[3];
    const float* b1f   = (const float*)d_in[4];
    const float* Wih1b = (const float*)d_in[5];
    const float* Whh1b = (const float*)d_in[6];
    const float* b1b   = (const float*)d_in[7];
    const float* Wih2f = (const float*)d_in[8];
    const float* Whh2f = (const float*)d_in[9];
    const float* b2f   = (const float*)d_in[10];
    const float* Wih2b = (const float*)d_in[11];
    const float* Whh2b = (const float*)d_in[12];
    const float* b2b   = (const float*)d_in[13];
    const float* Wlin  = (const float*)d_in[14];
    const float* blin  = (const float*)d_in[15];
    float* out = (float*)d_out;

    static bool s_attr_done = false;
    if (!s_attr_done) {
        cudaFuncSetAttribute(k_lstm, cudaFuncAttributeMaxDynamicSharedMemorySize, LSTM_SMEM);
        s_attr_done = true;
    }

    float *xg1f, *xg1b, *xg2f, *xg2b, *out1, *pool1, *out2;
    cudaGetSymbolAddress((void**)&xg1f,  g_xg1f);
    cudaGetSymbolAddress((void**)&xg1b,  g_xg1b);
    cudaGetSymbolAddress((void**)&xg2f,  g_xg2f);
    cudaGetSymbolAddress((void**)&xg2b,  g_xg2b);
    cudaGetSymbolAddress((void**)&out1,  g_out1);
    cudaGetSymbolAddress((void**)&pool1, g_pool1);
    cudaGetSymbolAddress((void**)&out2,  g_out2);

    const long long ot_xg = (long long)G4H * NB;
    const long long or_xg = NB;
    const long long ob_xg = 1;

    // zero masked-output buffers (graph replays must rewrite every call)
    k_zero<<<4096, 256>>>(out1, (size_t)NB * T1 * HDC);
    k_zero<<<4096, 256>>>(out2, (size_t)NB * T2 * HDC);

    // layer-1 gate projections: M=1024, N=(2000 t x 32 b), K=80
    k_proj<<<dim3(G4H / 256, T1), 128>>>(x, Wih1f, b1f, xg1f, T1, D1, ot_xg, or_xg, ob_xg);
    k_proj<<<dim3(G4H / 256, T1), 128>>>(x, Wih1b, b1b, xg1b, T1, D1, ot_xg, or_xg, ob_xg);

    // layer-1 recurrence
    k_init_rec<<<1, 256>>>();
    k_lstm<<<128, 128, LSTM_SMEM>>>(xg1f, xg1b, Whh1f, Whh1b, xlen, 0, out1, T1);

    // max-pool stride 2
    k_pool<<<2048, 256>>>(out1, pool1);

    // layer-2 gate projections: M=1024, K=512
    k_proj<<<dim3(G4H / 256, T2), 128>>>(pool1, Wih2f, b2f, xg2f, T2, HDC, ot_xg, or_xg, ob_xg);
    k_proj<<<dim3(G4H / 256, T2), 128>>>(pool1, Wih2b, b2b, xg2b, T2, HDC, ot_xg, or_xg, ob_xg);

    // layer-2 recurrence (lengths = x_len >> 1)
    k_init_rec<<<1, 256>>>();
    k_lstm<<<128, 128, LSTM_SMEM>>>(xg2f, xg2b, Whh2f, Whh2b, xlen, 1, out2, T2);

    // final linear: out[b][t][o] -> M=512, K=512, store-along-row mode
    k_proj<<<dim3(OUTC / 256, T2), 128>>>(out2, Wlin, blin, out, T2, HDC,
                                          (long long)OUTC, 1LL, (long long)T2 * OUTC);

    // lens = x_len // 2 appended as float
    if (out_size > NB * T2 * OUTC) {
        k_lens<<<1, 32>>>(xlen, out + (size_t)NB * T2 * OUTC);
    }
}

// round 9
// speedup vs baseline: 1.9343x; 1.0138x over previous
#include <cuda_runtime.h>
#include <cuda_bf16.h>
#include <cstdint>
#include <cstddef>
#include <math.h>

#define NB   32      // batch
#define T1   2000
#define T2   1000
#define D1   80
#define HH   256     // hidden per direction
#define G4H  1024    // 4*H gate rows
#define HDC  512
#define OUTC 512
#define CLSZ 16      // cluster size = blocks per group (h-shards)

typedef unsigned long long ull;

// ---------------- f32x2 packed-FMA helpers (Blackwell FFMA2) -----------------
__device__ __forceinline__ void fma2(ull& d, ull a, ull b) {
    asm("fma.rn.f32x2 %0, %1, %2, %3;" : "=l"(d) : "l"(a), "l"(b), "l"(d));
}
__device__ __forceinline__ ull dup2(float x) {
    ull r; asm("mov.b64 %0, {%1, %1};" : "=l"(r) : "f"(x)); return r;
}
__device__ __forceinline__ float2 unp2(ull v) {
    float2 r; asm("mov.b64 {%0, %1}, %2;" : "=f"(r.x), "=f"(r.y) : "l"(v)); return r;
}
__device__ __forceinline__ uint32_t smem_u32(const void* p) {
    uint32_t a;
    asm("{ .reg .u64 t; cvta.to.shared.u64 t, %1; cvt.u32.u64 %0, t; }" : "=r"(a) : "l"(p));
    return a;
}
__device__ __forceinline__ uint32_t mapa_u32(uint32_t addr, int rank) {
    uint32_t r;
    asm("mapa.shared::cluster.u32 %0, %1, %2;" : "=r"(r) : "r"(addr), "r"(rank));
    return r;
}

// ---------------- device scratch ---------------------------------------------
__device__ float g_xg1f[(size_t)T1 * G4H * NB];   // [t][gate_row][b]
__device__ float g_xg1b[(size_t)T1 * G4H * NB];
__device__ float g_xg2f[(size_t)T2 * G4H * NB];
__device__ float g_xg2b[(size_t)T2 * G4H * NB];
__device__ float g_out1[(size_t)NB * T1 * HDC];   // [b][t][ch]
__device__ float g_pool1[(size_t)NB * T2 * HDC];
__device__ float g_out2[(size_t)NB * T2 * HDC];

// ---------------- small helpers ---------------------------------------------
__global__ void k_zero(float* __restrict__ p, size_t n) {
    size_t i = (size_t)blockIdx.x * blockDim.x + threadIdx.x;
    size_t st = (size_t)gridDim.x * blockDim.x;
    for (; i < n; i += st) p[i] = 0.f;
}

__global__ void k_pool(const float* __restrict__ in, float* __restrict__ out) {
    size_t n = (size_t)NB * T2 * HDC;
    size_t i = (size_t)blockIdx.x * blockDim.x + threadIdx.x;
    size_t st = (size_t)gridDim.x * blockDim.x;
    for (; i < n; i += st) {
        int c  = (int)(i % HDC);
        size_t r = i / HDC;
        int tp = (int)(r % T2);
        int b  = (int)(r / T2);
        const float* p = in + ((size_t)b * T1 + 2 * (size_t)tp) * HDC + c;
        out[i] = fmaxf(p[0], p[HDC]);
    }
}

__global__ void k_lens(const int* __restrict__ xlen, float* __restrict__ out) {
    int i = threadIdx.x;
    if (i < NB) out[i] = (float)(xlen[i] >> 1);
}

// ---------------- projection / linear GEMM (frozen — proven) -----------------
__global__ void __launch_bounds__(128, 2) k_proj(
    const float* __restrict__ X, const float* __restrict__ W,
    const float* __restrict__ bias, float* __restrict__ out,
    int Tt, int K, long long ot, long long orr, long long ob)
{
    __shared__ __align__(16) float a_sh[16][256];
    __shared__ __align__(16) float b_sh[16][32];

    const int t    = blockIdx.y;
    const int row0 = blockIdx.x * 256;
    const int tid  = threadIdx.x;
    const int rowg = tid >> 2;
    const int colg = tid & 3;

    ull acc[4][8];
#pragma unroll
    for (int i = 0; i < 4; i++)
#pragma unroll
        for (int j = 0; j < 8; j++) acc[i][j] = 0ull;

    for (int k0 = 0; k0 < K; k0 += 16) {
        {
            const float* wp = W + (size_t)(row0 + tid) * K + k0;
            float4 v0 = ((const float4*)wp)[0];
            float4 v1 = ((const float4*)wp)[1];
            float4 v2 = ((const float4*)wp)[2];
            float4 v3 = ((const float4*)wp)[3];
            a_sh[ 0][tid] = v0.x; a_sh[ 1][tid] = v0.y; a_sh[ 2][tid] = v0.z; a_sh[ 3][tid] = v0.w;
            a_sh[ 4][tid] = v1.x; a_sh[ 5][tid] = v1.y; a_sh[ 6][tid] = v1.z; a_sh[ 7][tid] = v1.w;
            a_sh[ 8][tid] = v2.x; a_sh[ 9][tid] = v2.y; a_sh[10][tid] = v2.z; a_sh[11][tid] = v2.w;
            a_sh[12][tid] = v3.x; a_sh[13][tid] = v3.y; a_sh[14][tid] = v3.z; a_sh[15][tid] = v3.w;
            wp += (size_t)128 * K;
            v0 = ((const float4*)wp)[0];
            v1 = ((const float4*)wp)[1];
            v2 = ((const float4*)wp)[2];
            v3 = ((const float4*)wp)[3];
            const int r2 = tid + 128;
            a_sh[ 0][r2] = v0.x; a_sh[ 1][r2] = v0.y; a_sh[ 2][r2] = v0.z; a_sh[ 3][r2] = v0.w;
            a_sh[ 4][r2] = v1.x; a_sh[ 5][r2] = v1.y; a_sh[ 6][r2] = v1.z; a_sh[ 7][r2] = v1.w;
            a_sh[ 8][r2] = v2.x; a_sh[ 9][r2] = v2.y; a_sh[10][r2] = v2.z; a_sh[11][r2] = v2.w;
            a_sh[12][r2] = v3.x; a_sh[13][r2] = v3.y; a_sh[14][r2] = v3.z; a_sh[15][r2] = v3.w;
        }
        {
            const int bb = tid >> 2, ko = (tid & 3) * 4;
            const float* xp = X + ((size_t)bb * Tt + t) * K + k0 + ko;
            float4 u = *(const float4*)xp;
            b_sh[ko + 0][bb] = u.x; b_sh[ko + 1][bb] = u.y;
            b_sh[ko + 2][bb] = u.z; b_sh[ko + 3][bb] = u.w;
        }
        __syncthreads();
#pragma unroll
        for (int kk = 0; kk < 16; kk++) {
            ulonglong2 a01 = *(const ulonglong2*)&a_sh[kk][rowg * 8];
            ulonglong2 a23 = *(const ulonglong2*)&a_sh[kk][rowg * 8 + 4];
            float4 u0 = *(const float4*)&b_sh[kk][colg * 8];
            float4 u1 = *(const float4*)&b_sh[kk][colg * 8 + 4];
            ull b0 = dup2(u0.x), b1 = dup2(u0.y), b2 = dup2(u0.z), b3 = dup2(u0.w);
            ull b4 = dup2(u1.x), b5 = dup2(u1.y), b6 = dup2(u1.z), b7 = dup2(u1.w);
            fma2(acc[0][0], a01.x, b0); fma2(acc[0][1], a01.x, b1);
            fma2(acc[0][2], a01.x, b2); fma2(acc[0][3], a01.x, b3);
            fma2(acc[0][4], a01.x, b4); fma2(acc[0][5], a01.x, b5);
            fma2(acc[0][6], a01.x, b6); fma2(acc[0][7], a01.x, b7);
            fma2(acc[1][0], a01.y, b0); fma2(acc[1][1], a01.y, b1);
            fma2(acc[1][2], a01.y, b2); fma2(acc[1][3], a01.y, b3);
            fma2(acc[1][4], a01.y, b4); fma2(acc[1][5], a01.y, b5);
            fma2(acc[1][6], a01.y, b6); fma2(acc[1][7], a01.y, b7);
            fma2(acc[2][0], a23.x, b0); fma2(acc[2][1], a23.x, b1);
            fma2(acc[2][2], a23.x, b2); fma2(acc[2][3], a23.x, b3);
            fma2(acc[2][4], a23.x, b4); fma2(acc[2][5], a23.x, b5);
            fma2(acc[2][6], a23.x, b6); fma2(acc[2][7], a23.x, b7);
            fma2(acc[3][0], a23.y, b0); fma2(acc[3][1], a23.y, b1);
            fma2(acc[3][2], a23.y, b2); fma2(acc[3][3], a23.y, b3);
            fma2(acc[3][4], a23.y, b4); fma2(acc[3][5], a23.y, b5);
            fma2(acc[3][6], a23.y, b6); fma2(acc[3][7], a23.y, b7);
        }
        __syncthreads();
    }

    const int rbase = row0 + rowg * 8;
    float4 bv0 = *(const float4*)&bias[rbase];
    float4 bv1 = *(const float4*)&bias[rbase + 4];
    const float bv[8] = {bv0.x, bv0.y, bv0.z, bv0.w, bv1.x, bv1.y, bv1.z, bv1.w};

    if (ob == 1) {
        float* op = out + (size_t)t * ot + (size_t)rbase * orr + colg * 8;
#pragma unroll
        for (int rp = 0; rp < 4; rp++) {
            float va[8], vb[8];
#pragma unroll
            for (int c = 0; c < 8; c++) {
                float2 u = unp2(acc[rp][c]);
                va[c] = u.x + bv[2 * rp];
                vb[c] = u.y + bv[2 * rp + 1];
            }
            float* r0 = op + (size_t)(2 * rp) * orr;
            float* r1 = op + (size_t)(2 * rp + 1) * orr;
            *(float4*)r0       = make_float4(va[0], va[1], va[2], va[3]);
            *(float4*)(r0 + 4) = make_float4(va[4], va[5], va[6], va[7]);
            *(float4*)r1       = make_float4(vb[0], vb[1], vb[2], vb[3]);
            *(float4*)(r1 + 4) = make_float4(vb[4], vb[5], vb[6], vb[7]);
        }
    } else {
        float* op = out + (size_t)t * ot + rbase;
#pragma unroll
        for (int c = 0; c < 8; c++) {
            size_t boff = (size_t)(colg * 8 + c) * ob;
            float2 p0 = unp2(acc[0][c]);
            float2 p1 = unp2(acc[1][c]);
            float2 p2 = unp2(acc[2][c]);
            float2 p3 = unp2(acc[3][c]);
            *(float4*)(op + boff)     = make_float4(p0.x + bv[0], p0.y + bv[1], p1.x + bv[2], p1.y + bv[3]);
            *(float4*)(op + boff + 4) = make_float4(p2.x + bv[4], p2.y + bv[5], p3.x + bv[6], p3.y + bv[7]);
        }
    }
}

// ---------------- persistent recurrent LSTM: DSMEM cluster groups ------------
__device__ __forceinline__ float fsig(float x) {
    return 1.f / (1.f + __expf(-x));
}
__device__ __forceinline__ float ftanh(float x) {
    float e = __expf(2.f * x);
    return 1.f - 2.f / (e + 1.f);
}

// smem: w_sh 64KB [k(256)][row(64)] | h_sh 16KB [parity(2)][k(256)][b(8)] | part [4][64][9]
#define PART_STRIDE 9
#define HBUF_FLOATS (HH * 8)
#define LSTM_SMEM (65536 + 2 * HBUF_FLOATS * 4 + 4 * 64 * PART_STRIDE * 4)

__global__ void __launch_bounds__(128, 1) k_lstm(
    const float* __restrict__ xgF, const float* __restrict__ xgB,
    const float* __restrict__ WhhF, const float* __restrict__ WhhB,
    const int* __restrict__ xlen, int lenShift,
    float* __restrict__ out, int Tt)
{
    extern __shared__ __align__(16) char dynsmem[];
    float* w_sh = (float*)dynsmem;                       // [256][64]
    float* h_sh = (float*)(dynsmem + 65536);             // [2][256][8]
    float* part = (float*)(dynsmem + 65536 + 2 * HBUF_FLOATS * 4);

    const int bx  = (int)blockIdx.x;
    const int dir = bx >> 6;           // 0 fwd, 1 bwd
    const int bs  = (bx >> 4) & 3;     // batch shard (8 batches)
    const int hs  = bx & 15;           // h shard == cluster rank

    const float* xg  = dir ? xgB : xgF;
    const float* Whh = dir ? WhhB : WhhF;

    const int tid  = threadIdx.x;
    const int warp = tid >> 5, lane = tid & 31;
    const int q    = lane & 15;        // row quad (4 rows)
    const int bg4  = lane >> 4;        // batch group of 4 (0,1)
    const int kbase = warp * 64;

    // ---- zero h buffers (both parities) ----
    {
        float4* hz = (float4*)h_sh;
#pragma unroll
        for (int j = tid; j < 2 * HBUF_FLOATS / 4; j += 128) hz[j] = make_float4(0.f, 0.f, 0.f, 0.f);
    }

    // ---- one-time: stage Whh slice [256 k][64 local rows] ----
    {
        const int r  = tid & 63;
        const int ko = (tid >> 6) * 128;
        const int grow = (r >> 4) * HH + hs * 16 + (r & 15);
        const float* wp = Whh + (size_t)grow * HH + ko;
#pragma unroll
        for (int j = 0; j < 128; j += 4) {
            float4 v = *(const float4*)(wp + j);
            w_sh[(size_t)(ko + j + 0) * 64 + r] = v.x;
            w_sh[(size_t)(ko + j + 1) * 64 + r] = v.y;
            w_sh[(size_t)(ko + j + 2) * 64 + r] = v.z;
            w_sh[(size_t)(ko + j + 3) * 64 + r] = v.w;
        }
    }

    // ---- peer DSMEM addresses for the h scatter (own stripe, all 16 CTAs) ----
    const uint32_t h_u32 = smem_u32(h_sh);
    uint32_t peer[CLSZ];
#pragma unroll
    for (int r = 0; r < CLSZ; r++) peer[r] = mapa_u32(h_u32, r);
    // this thread's element within a buffer: hs*128 + tid  (hk*8 + bl_p)
    const uint32_t selfOff = ((uint32_t)(hs * 128 + tid)) * 4u;

    // ---- pointwise role ----
    const int hl_p = tid >> 3;             // 0..15
    const int bl_p = tid & 7;              // 0..7
    const int hk   = hs * 16 + hl_p;
    const int b_g  = bs * 8 + bl_p;
    const int len_b = xlen[b_g] >> lenShift;
    int gmax = 0;
#pragma unroll
    for (int j = 0; j < 8; j++) {
        int l = xlen[bs * 8 + j] >> lenShift;
        gmax = (l > gmax) ? l : gmax;
    }
    float c_st = 0.f, h_st = 0.f;

    __syncthreads();
    // all CTAs' h buffers zeroed before any peer writes
    asm volatile("barrier.cluster.arrive.aligned;" ::: "memory");
    asm volatile("barrier.cluster.wait.aligned;" ::: "memory");

    // gate-input prefetch for step 0
    float xg0, xg1, xg2, xg3;
    {
        int tx = dir ? (len_b - 1) : 0;
        if (tx < 0) tx = 0;
        const float* xp = xg + (size_t)tx * (G4H * NB) + (size_t)hk * NB + b_g;
        xg0 = __ldg(xp);
        xg1 = __ldg(xp + 256 * NB);
        xg2 = __ldg(xp + 512 * NB);
        xg3 = __ldg(xp + 768 * NB);
    }

    for (int s = 0; s < gmax; s++) {
        const int bufp = s & 1;

        // ---- GEMM slice from local h_sh[bufp] ----
        ull acc[2][4] = {};
        const float* wq = w_sh + (size_t)kbase * 64 + q * 4;
        const float* hq = h_sh + (size_t)bufp * HBUF_FLOATS + (size_t)kbase * 8 + bg4 * 4;
#pragma unroll 16
        for (int k = 0; k < 64; k++) {
            ulonglong2 wv = *(const ulonglong2*)(wq + (size_t)k * 64);
            float4 hv = *(const float4*)(hq + (size_t)k * 8);
            ull h0 = dup2(hv.x), h1 = dup2(hv.y), h2 = dup2(hv.z), h3 = dup2(hv.w);
            fma2(acc[0][0], wv.x, h0); fma2(acc[0][1], wv.x, h1);
            fma2(acc[0][2], wv.x, h2); fma2(acc[0][3], wv.x, h3);
            fma2(acc[1][0], wv.y, h0); fma2(acc[1][1], wv.y, h1);
            fma2(acc[1][2], wv.y, h2); fma2(acc[1][3], wv.y, h3);
        }

        // ---- partials ----
#pragma unroll
        for (int i = 0; i < 2; i++) {
#pragma unroll
            for (int j = 0; j < 4; j++) {
                float2 u = unp2(acc[i][j]);
                float* p0 = part + ((size_t)warp * 64 + q * 4 + 2 * i) * PART_STRIDE + bg4 * 4 + j;
                p0[0] = u.x;
                p0[PART_STRIDE] = u.y;
            }
        }
        __syncthreads();

        // ---- reduce + pointwise for (hl_p, bl_p) ----
        float g0 = xg0, g1 = xg1, g2 = xg2, g3 = xg3;
#pragma unroll
        for (int w = 0; w < 4; w++) {
            const float* pr = part + (size_t)w * 64 * PART_STRIDE + bl_p;
            g0 += pr[(0  + hl_p) * PART_STRIDE];
            g1 += pr[(16 + hl_p) * PART_STRIDE];
            g2 += pr[(32 + hl_p) * PART_STRIDE];
            g3 += pr[(48 + hl_p) * PART_STRIDE];
        }
        float ig = fsig(g0);
        float fg = fsig(g1);
        float gg = ftanh(g2);
        float og = fsig(g3);
        float c_n = fg * c_st + ig * gg;
        float h_n = og * ftanh(c_n);
        if (s < len_b) {
            c_st = c_n; h_st = h_n;
            int t_o = dir ? (len_b - 1 - s) : s;
            out[((size_t)b_g * Tt + t_o) * HDC + dir * HH + hk] = h_n;
        }

        // ---- scatter h to all 16 CTAs' h_sh[bufp^1] via DSMEM ----
        {
            const uint32_t off = (uint32_t)((bufp ^ 1) * HBUF_FLOATS * 4) + selfOff;
            const float hv = h_st;
#pragma unroll
            for (int r = 0; r < CLSZ; r++) {
                asm volatile("st.shared::cluster.f32 [%0], %1;"
                             :: "r"(peer[r] + off), "f"(hv) : "memory");
            }
        }

        // release my stores; overlap xg prefetch with peers finishing
        asm volatile("barrier.cluster.arrive.aligned;" ::: "memory");
        {
            int sn = s + 1;
            int tx = dir ? (len_b - 1 - sn) : sn;
            if (tx < 0) tx = 0;
            if (tx >= Tt) tx = Tt - 1;
            const float* xp = xg + (size_t)tx * (G4H * NB) + (size_t)hk * NB + b_g;
            xg0 = __ldg(xp);
            xg1 = __ldg(xp + 256 * NB);
            xg2 = __ldg(xp + 512 * NB);
            xg3 = __ldg(xp + 768 * NB);
        }
        asm volatile("barrier.cluster.wait.aligned;" ::: "memory");
    }
}

// ---------------- host orchestration ----------------------------------------
extern "C" void kernel_launch(void* const* d_in, const int* in_sizes, int n_in,
                              void* d_out, int out_size) {
    const float* x     = (const float*)d_in[0];
    const int*   xlen  = (const int*)d_in[1];
    const float* Wih1f = (const float*)d_in[2];
    const float* Whh1f = (const float*)d_in[3];
    const float* b1f   = (const float*)d_in[4];
    const float* Wih1b = (const float*)d_in[5];
    const float* Whh1b = (const float*)d_in[6];
    const float* b1b   = (const float*)d_in[7];
    const float* Wih2f = (const float*)d_in[8];
    const float* Whh2f = (const float*)d_in[9];
    const float* b2f   = (const float*)d_in[10];
    const float* Wih2b = (const float*)d_in[11];
    const float* Whh2b = (const float*)d_in[12];
    const float* b2b   = (const float*)d_in[13];
    const float* Wlin  = (const float*)d_in[14];
    const float* blin  = (const float*)d_in[15];
    float* out = (float*)d_out;

    static bool s_attr_done = false;
    if (!s_attr_done) {
        cudaFuncSetAttribute(k_lstm, cudaFuncAttributeMaxDynamicSharedMemorySize, LSTM_SMEM);
        cudaFuncSetAttribute(k_lstm, cudaFuncAttributeNonPortableClusterSizeAllowed, 1);
        s_attr_done = true;
    }

    float *xg1f, *xg1b, *xg2f, *xg2b, *out1, *pool1, *out2;
    cudaGetSymbolAddress((void**)&xg1f,  g_xg1f);
    cudaGetSymbolAddress((void**)&xg1b,  g_xg1b);
    cudaGetSymbolAddress((void**)&xg2f,  g_xg2f);
    cudaGetSymbolAddress((void**)&xg2b,  g_xg2b);
    cudaGetSymbolAddress((void**)&out1,  g_out1);
    cudaGetSymbolAddress((void**)&pool1, g_pool1);
    cudaGetSymbolAddress((void**)&out2,  g_out2);

    const long long ot_xg = (long long)G4H * NB;
    const long long or_xg = NB;
    const long long ob_xg = 1;

    // zero masked-output buffers (graph replays must rewrite every call)
    k_zero<<<4096, 256>>>(out1, (size_t)NB * T1 * HDC);
    k_zero<<<4096, 256>>>(out2, (size_t)NB * T2 * HDC);

    // layer-1 gate projections: M=1024, N=(2000 t x 32 b), K=80
    k_proj<<<dim3(G4H / 256, T1), 128>>>(x, Wih1f, b1f, xg1f, T1, D1, ot_xg, or_xg, ob_xg);
    k_proj<<<dim3(G4H / 256, T1), 128>>>(x, Wih1b, b1b, xg1b, T1, D1, ot_xg, or_xg, ob_xg);

    // cluster launch helper
    auto launch_lstm = [&](const float* xf, const float* xb,
                           const float* wf, const float* wb,
                           int shift, float* o, int Tt) {
        cudaLaunchConfig_t cfg = {};
        cfg.gridDim  = dim3(128, 1, 1);
        cfg.blockDim = dim3(128, 1, 1);
        cfg.dynamicSmemBytes = LSTM_SMEM;
        cfg.stream = 0;
        cudaLaunchAttribute attrs[1];
        attrs[0].id = cudaLaunchAttributeClusterDimension;
        attrs[0].val.clusterDim.x = CLSZ;
        attrs[0].val.clusterDim.y = 1;
        attrs[0].val.clusterDim.z = 1;
        cfg.attrs = attrs;
        cfg.numAttrs = 1;
        cudaLaunchKernelEx(&cfg, k_lstm, xf, xb, wf, wb, xlen, shift, o, Tt);
    };

    // layer-1 recurrence
    launch_lstm(xg1f, xg1b, Whh1f, Whh1b, 0, out1, T1);

    // max-pool stride 2
    k_pool<<<2048, 256>>>(out1, pool1);

    // layer-2 gate projections: M=1024, K=512
    k_proj<<<dim3(G4H / 256, T2), 128>>>(pool1, Wih2f, b2f, xg2f, T2, HDC, ot_xg, or_xg, ob_xg);
    k_proj<<<dim3(G4H / 256, T2), 128>>>(pool1, Wih2b, b2b, xg2b, T2, HDC, ot_xg, or_xg, ob_xg);

    // layer-2 recurrence (lengths = x_len >> 1)
    launch_lstm(xg2f, xg2b, Whh2f, Whh2b, 1, out2, T2);

    // final linear: out[b][t][o] -> M=512, K=512, store-along-row mode
    k_proj<<<dim3(OUTC / 256, T2), 128>>>(out2, Wlin, blin, out, T2, HDC,
                                          (long long)OUTC, 1LL, (long long)T2 * OUTC);

    // lens = x_len // 2 appended as float
    if (out_size > NB * T2 * OUTC) {
        k_lens<<<1, 32>>>(xlen, out + (size_t)NB * T2 * OUTC);
    }
}